// round 1
// baseline (speedup 1.0000x reference)
#include <cuda_runtime.h>
#include <math.h>

#define Nn 100000
#define Ee 3200000
#define Hh 512
#define Bb 512
#define GIN 1028   // 2*H + 4
#define RWS 4      // rows per MLP block

// ---------------- scratch (static device memory, no allocation) ----------------
__device__ int   g_off[Bb + 1];
__device__ int   g_nedges[Bb];
__device__ float g_feat[Bb][GIN];   // [pooled_ggnn | pooled_appnp | complexity4]
__device__ float g_stats[Bb][3];    // dot, |g|^2, |a|^2 of pooled means
__device__ float g_w[Bb][2];        // softmax gate weights

// ---------------- 1) graph boundaries from sorted batch + zero nedges ----------
__global__ void k_offsets(const int* __restrict__ batch) {
    int i = blockIdx.x * blockDim.x + threadIdx.x;
    if (i < Bb) g_nedges[i] = 0;
    if (i >= Nn) return;
    int c = batch[i];
    int p = (i == 0) ? -1 : batch[i - 1];
    for (int b = p + 1; b <= c; b++) g_off[b] = i;
    if (i == Nn - 1) {
        for (int b = c + 1; b <= Bb; b++) g_off[b] = Nn;
    }
}

// ---------------- 2) same-graph edge histogram --------------------------------
__global__ void k_edges(const int* __restrict__ ei, const int* __restrict__ batch) {
    __shared__ int hist[Bb];
    for (int i = threadIdx.x; i < Bb; i += blockDim.x) hist[i] = 0;
    __syncthreads();
    const int* src = ei;
    const int* dst = ei + Ee;
    int stride = gridDim.x * blockDim.x;
    for (int e = blockIdx.x * blockDim.x + threadIdx.x; e < Ee; e += stride) {
        int s = src[e], d = dst[e];
        int sg = batch[s], dg = batch[d];
        if (sg == dg) atomicAdd(&hist[sg], 1);
    }
    __syncthreads();
    for (int i = threadIdx.x; i < Bb; i += blockDim.x) {
        int v = hist[i];
        if (v) atomicAdd(&g_nedges[i], v);
    }
}

// ---------------- 3) segment-mean pooling (one block per graph) ----------------
__global__ void k_pool(const float* __restrict__ xg, const float* __restrict__ xa) {
    int b = blockIdx.x;
    int t = threadIdx.x;             // 128 threads, thread t owns cols 4t..4t+3
    int s = g_off[b], e = g_off[b + 1];
    float4 sg = make_float4(0.f, 0.f, 0.f, 0.f);
    float4 sa = make_float4(0.f, 0.f, 0.f, 0.f);
    const float4* pg = ((const float4*)xg) + t;
    const float4* pa = ((const float4*)xa) + t;
    for (int r = s; r < e; r++) {
        float4 vg = pg[(size_t)r * 128];
        float4 va = pa[(size_t)r * 128];
        sg.x += vg.x; sg.y += vg.y; sg.z += vg.z; sg.w += vg.w;
        sa.x += va.x; sa.y += va.y; sa.z += va.z; sa.w += va.w;
    }
    float cnt = (float)(e - s);
    float inv = 1.f / fmaxf(cnt, 1.f);
    float4 mg = make_float4(sg.x * inv, sg.y * inv, sg.z * inv, sg.w * inv);
    float4 ma = make_float4(sa.x * inv, sa.y * inv, sa.z * inv, sa.w * inv);
    *(float4*)&g_feat[b][4 * t]        = mg;
    *(float4*)&g_feat[b][Hh + 4 * t]   = ma;

    // block-reduce dot, |g|^2, |a|^2 of the pooled means
    float dot = mg.x * ma.x + mg.y * ma.y + mg.z * ma.z + mg.w * ma.w;
    float n2g = mg.x * mg.x + mg.y * mg.y + mg.z * mg.z + mg.w * mg.w;
    float n2a = ma.x * ma.x + ma.y * ma.y + ma.z * ma.z + ma.w * ma.w;
    __shared__ float red[3][4];
    int lane = t & 31, wid = t >> 5;
    #pragma unroll
    for (int o = 16; o > 0; o >>= 1) {
        dot += __shfl_down_sync(0xFFFFFFFFu, dot, o);
        n2g += __shfl_down_sync(0xFFFFFFFFu, n2g, o);
        n2a += __shfl_down_sync(0xFFFFFFFFu, n2a, o);
    }
    if (lane == 0) { red[0][wid] = dot; red[1][wid] = n2g; red[2][wid] = n2a; }
    __syncthreads();
    if (t == 0) {
        g_stats[b][0] = red[0][0] + red[0][1] + red[0][2] + red[0][3];
        g_stats[b][1] = red[1][0] + red[1][1] + red[1][2] + red[1][3];
        g_stats[b][2] = red[2][0] + red[2][1] + red[2][2] + red[2][3];
    }
}

// ---------------- 4) complexity features --------------------------------------
__global__ void k_complex() {
    int b = blockIdx.x * blockDim.x + threadIdx.x;
    if (b >= Bb) return;
    float cnt = (float)(g_off[b + 1] - g_off[b]);
    float ne  = (float)g_nedges[b];
    float scale   = logf(cnt + 1.f) * (1.f / logf(501.0f));
    float density = ne / (cnt * (cnt - 1.f) + 1e-8f);
    float avgdeg  = ne / (cnt + 1e-8f);
    float avn     = fminf(avgdeg * 0.1f, 1.f);
    float dot = g_stats[b][0], n2g = g_stats[b][1], n2a = g_stats[b][2];
    float na = fmaxf(sqrtf(n2g), 1e-8f);
    float nb = fmaxf(sqrtf(n2a), 1e-8f);
    float cosv = dot / (na * nb);
    float dvg = (1.f - cosv) * 0.5f;
    g_feat[b][2 * Hh + 0] = scale;
    g_feat[b][2 * Hh + 1] = density;
    g_feat[b][2 * Hh + 2] = avn;
    g_feat[b][2 * Hh + 3] = dvg;
}

// ---------------- 5) fused MLP: GEMM1 + LN + relu + GEMM2 + relu + GEMM3 + softmax
__global__ void __launch_bounds__(256) k_mlp(
    const float* __restrict__ W1, const float* __restrict__ b1,
    const float* __restrict__ lng, const float* __restrict__ lnb,
    const float* __restrict__ W2, const float* __restrict__ b2,
    const float* __restrict__ W3, const float* __restrict__ b3)
{
    __shared__ float gs[RWS][GIN];      // input rows
    __shared__ float ts[RWS][Hh];       // post-LN+relu
    __shared__ float red[RWS][8];
    __shared__ float mu_s[RWS], rs_s[RWS];
    __shared__ float red3[8][RWS][2];
    __shared__ float raw_s[RWS][2];

    int t = threadIdx.x;                // 256 threads
    int row0 = blockIdx.x * RWS;
    int lane = t & 31, wid = t >> 5;

    for (int i = t; i < RWS * GIN; i += 256) {
        int r = i / GIN, k = i - r * GIN;
        gs[r][k] = g_feat[row0 + r][k];
    }
    __syncthreads();

    // ---- layer 1: h = g @ W1 + b1 ; each thread owns cols 2t, 2t+1
    float2 acc[RWS];
    #pragma unroll
    for (int r = 0; r < RWS; r++) acc[r] = make_float2(0.f, 0.f);
    const float2* W1v = (const float2*)W1;  // W1[k][2t..2t+1] = W1v[k*256+t]
    for (int k = 0; k < GIN; k += 4) {
        float ga[RWS][4];
        #pragma unroll
        for (int r = 0; r < RWS; r++) {
            float4 q = *(const float4*)&gs[r][k];
            ga[r][0] = q.x; ga[r][1] = q.y; ga[r][2] = q.z; ga[r][3] = q.w;
        }
        #pragma unroll
        for (int kk = 0; kk < 4; kk++) {
            float2 w = W1v[(size_t)(k + kk) * 256 + t];
            #pragma unroll
            for (int r = 0; r < RWS; r++) {
                acc[r].x += ga[r][kk] * w.x;
                acc[r].y += ga[r][kk] * w.y;
            }
        }
    }
    float2 bb = ((const float2*)b1)[t];
    float2 h[RWS];
    #pragma unroll
    for (int r = 0; r < RWS; r++) { h[r].x = acc[r].x + bb.x; h[r].y = acc[r].y + bb.y; }

    // ---- layernorm (mean)
    #pragma unroll
    for (int r = 0; r < RWS; r++) {
        float p = h[r].x + h[r].y;
        #pragma unroll
        for (int o = 16; o > 0; o >>= 1) p += __shfl_down_sync(0xFFFFFFFFu, p, o);
        if (lane == 0) red[r][wid] = p;
    }
    __syncthreads();
    if (t < RWS) {
        float s = 0.f;
        #pragma unroll
        for (int w = 0; w < 8; w++) s += red[t][w];
        mu_s[t] = s * (1.f / (float)Hh);
    }
    __syncthreads();
    // ---- layernorm (var)
    #pragma unroll
    for (int r = 0; r < RWS; r++) {
        float dx = h[r].x - mu_s[r], dy = h[r].y - mu_s[r];
        float p = dx * dx + dy * dy;
        #pragma unroll
        for (int o = 16; o > 0; o >>= 1) p += __shfl_down_sync(0xFFFFFFFFu, p, o);
        if (lane == 0) red[r][wid] = p;
    }
    __syncthreads();
    if (t < RWS) {
        float s = 0.f;
        #pragma unroll
        for (int w = 0; w < 8; w++) s += red[t][w];
        rs_s[t] = rsqrtf(s * (1.f / (float)Hh) + 1e-5f);
    }
    __syncthreads();
    {
        float2 gv = ((const float2*)lng)[t];
        float2 bv = ((const float2*)lnb)[t];
        #pragma unroll
        for (int r = 0; r < RWS; r++) {
            float vx = (h[r].x - mu_s[r]) * rs_s[r] * gv.x + bv.x;
            float vy = (h[r].y - mu_s[r]) * rs_s[r] * gv.y + bv.y;
            ts[r][2 * t]     = fmaxf(vx, 0.f);
            ts[r][2 * t + 1] = fmaxf(vy, 0.f);
        }
    }
    __syncthreads();

    // ---- layer 2: u = relu(ts @ W2 + b2); thread t owns output col t (256 cols)
    float u[RWS];
    #pragma unroll
    for (int r = 0; r < RWS; r++) u[r] = 0.f;
    for (int k = 0; k < Hh; k += 4) {
        float ta[RWS][4];
        #pragma unroll
        for (int r = 0; r < RWS; r++) {
            float4 q = *(const float4*)&ts[r][k];
            ta[r][0] = q.x; ta[r][1] = q.y; ta[r][2] = q.z; ta[r][3] = q.w;
        }
        #pragma unroll
        for (int kk = 0; kk < 4; kk++) {
            float w = W2[(size_t)(k + kk) * 256 + t];
            #pragma unroll
            for (int r = 0; r < RWS; r++) u[r] += ta[r][kk] * w;
        }
    }
    float bt = b2[t];
    #pragma unroll
    for (int r = 0; r < RWS; r++) u[r] = fmaxf(u[r] + bt, 0.f);

    // ---- layer 3: raw[r][c] = sum_j u[r][j]*W3[j][c] + b3[c]
    float w30 = W3[2 * t], w31 = W3[2 * t + 1];
    float p0[RWS], p1[RWS];
    #pragma unroll
    for (int r = 0; r < RWS; r++) { p0[r] = u[r] * w30; p1[r] = u[r] * w31; }
    #pragma unroll
    for (int o = 16; o > 0; o >>= 1) {
        #pragma unroll
        for (int r = 0; r < RWS; r++) {
            p0[r] += __shfl_down_sync(0xFFFFFFFFu, p0[r], o);
            p1[r] += __shfl_down_sync(0xFFFFFFFFu, p1[r], o);
        }
    }
    if (lane == 0) {
        #pragma unroll
        for (int r = 0; r < RWS; r++) { red3[wid][r][0] = p0[r]; red3[wid][r][1] = p1[r]; }
    }
    __syncthreads();
    if (t < RWS * 2) {
        int r = t >> 1, c = t & 1;
        float s = 0.f;
        #pragma unroll
        for (int w = 0; w < 8; w++) s += red3[w][r][c];
        raw_s[r][c] = s + b3[c];
    }
    __syncthreads();
    if (t < RWS) {
        float r0 = raw_s[t][0], r1 = raw_s[t][1];
        float m = fmaxf(r0, r1);
        float e0 = expf(r0 - m), e1 = expf(r1 - m);
        float inv = 1.f / (e0 + e1);
        g_w[row0 + t][0] = e0 * inv;
        g_w[row0 + t][1] = e1 * inv;
    }
}

// ---------------- 6) gated fusion ----------------------------------------------
__global__ void k_fuse(const float* __restrict__ xg, const float* __restrict__ xa,
                       const int* __restrict__ batch, float* __restrict__ out) {
    size_t i = (size_t)blockIdx.x * blockDim.x + threadIdx.x;   // float4 index
    if (i >= (size_t)Nn * 128) return;
    int n = (int)(i >> 7);
    int b = batch[n];
    float w0 = g_w[b][0], w1 = g_w[b][1];
    float4 g = ((const float4*)xg)[i];
    float4 a = ((const float4*)xa)[i];
    float4 o;
    o.x = w0 * g.x + w1 * a.x;
    o.y = w0 * g.y + w1 * a.y;
    o.z = w0 * g.z + w1 * a.z;
    o.w = w0 * g.w + w1 * a.w;
    ((float4*)out)[i] = o;
}

// ---------------- launch --------------------------------------------------------
extern "C" void kernel_launch(void* const* d_in, const int* in_sizes, int n_in,
                              void* d_out, int out_size) {
    const float* x_ggnn  = (const float*)d_in[0];
    const float* x_appnp = (const float*)d_in[1];
    const int*   edge    = (const int*)d_in[2];
    const int*   batch   = (const int*)d_in[3];
    const float* W1 = (const float*)d_in[4];
    const float* b1 = (const float*)d_in[5];
    const float* lng = (const float*)d_in[6];
    const float* lnb = (const float*)d_in[7];
    const float* W2 = (const float*)d_in[8];
    const float* b2 = (const float*)d_in[9];
    const float* W3 = (const float*)d_in[10];
    const float* b3 = (const float*)d_in[11];
    float* out = (float*)d_out;

    k_offsets<<<(Nn + 255) / 256, 256>>>(batch);
    k_edges<<<592, 256>>>(edge, batch);
    k_pool<<<Bb, 128>>>(x_ggnn, x_appnp);
    k_complex<<<2, 256>>>();
    k_mlp<<<Bb / RWS, 256>>>(W1, b1, lng, lnb, W2, b2, W3, b3);
    k_fuse<<<(Nn * 128 + 255) / 256, 256>>>(x_ggnn, x_appnp, batch, out);
}

// round 2
// speedup vs baseline: 1.0887x; 1.0887x over previous
#include <cuda_runtime.h>
#include <math.h>

#define Nn 100000
#define Ee 3200000
#define Hh 512
#define Bb 512
#define GIN 1028   // 2*H + 4
#define RWS 4      // rows per MLP block

// ---------------- scratch (static device memory, no allocation) ----------------
__device__ int   g_off[Bb + 1];
__device__ int   g_nedges[Bb];
__device__ float g_feat[Bb][GIN];   // [pooled_ggnn | pooled_appnp | complexity4]
__device__ float g_stats[Bb][3];    // dot, |g|^2, |a|^2 of pooled means
__device__ float g_w[Bb][2];        // softmax gate weights

// ---------------- 1) graph boundaries from sorted batch + zero nedges ----------
__global__ void k_offsets(const int* __restrict__ batch) {
    int i = blockIdx.x * blockDim.x + threadIdx.x;
    if (i < Bb) g_nedges[i] = 0;
    if (i >= Nn) return;
    int c = batch[i];
    int p = (i == 0) ? -1 : batch[i - 1];
    for (int b = p + 1; b <= c; b++) g_off[b] = i;
    if (i == Nn - 1) {
        for (int b = c + 1; b <= Bb; b++) g_off[b] = Nn;
    }
}

// ---------------- 2) same-graph edge histogram (int4-vectorized, one pass) -----
__global__ void __launch_bounds__(256) k_edges(const int* __restrict__ ei,
                                               const int* __restrict__ batch) {
    __shared__ int hist[Bb];
    for (int i = threadIdx.x; i < Bb; i += 256) hist[i] = 0;
    __syncthreads();
    const int4* src4 = (const int4*)ei;
    const int4* dst4 = (const int4*)(ei + Ee);
    int i = blockIdx.x * 256 + threadIdx.x;          // i < Ee/4 = 800000 exactly
    int4 s = __ldg(&src4[i]);
    int4 d = __ldg(&dst4[i]);
    int sg0 = __ldg(&batch[s.x]), sg1 = __ldg(&batch[s.y]);
    int sg2 = __ldg(&batch[s.z]), sg3 = __ldg(&batch[s.w]);
    int dg0 = __ldg(&batch[d.x]), dg1 = __ldg(&batch[d.y]);
    int dg2 = __ldg(&batch[d.z]), dg3 = __ldg(&batch[d.w]);
    if (sg0 == dg0) atomicAdd(&hist[sg0], 1);
    if (sg1 == dg1) atomicAdd(&hist[sg1], 1);
    if (sg2 == dg2) atomicAdd(&hist[sg2], 1);
    if (sg3 == dg3) atomicAdd(&hist[sg3], 1);
    __syncthreads();
    for (int b = threadIdx.x; b < Bb; b += 256) {
        int v = hist[b];
        if (v) atomicAdd(&g_nedges[b], v);
    }
}

// ---------------- 3) segment-mean pooling: 256 thr, split halves, 4-row unroll --
__global__ void __launch_bounds__(256) k_pool(const float* __restrict__ xg,
                                              const float* __restrict__ xa) {
    int b = blockIdx.x;
    int t = threadIdx.x;               // 256 threads
    int half = t >> 7;                 // 0 -> xg, 1 -> xa
    int c = t & 127;                   // float4 column within H
    int s0 = g_off[b], e0 = g_off[b + 1];

    const float4* p = ((const float4*)(half ? xa : xg)) + c;
    float4 acc = make_float4(0.f, 0.f, 0.f, 0.f);
    int r = s0;
    for (; r + 4 <= e0; r += 4) {
        float4 v0 = p[(size_t)(r + 0) * 128];
        float4 v1 = p[(size_t)(r + 1) * 128];
        float4 v2 = p[(size_t)(r + 2) * 128];
        float4 v3 = p[(size_t)(r + 3) * 128];
        acc.x += v0.x + v1.x + v2.x + v3.x;
        acc.y += v0.y + v1.y + v2.y + v3.y;
        acc.z += v0.z + v1.z + v2.z + v3.z;
        acc.w += v0.w + v1.w + v2.w + v3.w;
    }
    for (; r < e0; r++) {
        float4 v = p[(size_t)r * 128];
        acc.x += v.x; acc.y += v.y; acc.z += v.z; acc.w += v.w;
    }
    float inv = 1.f / fmaxf((float)(e0 - s0), 1.f);
    float4 m = make_float4(acc.x * inv, acc.y * inv, acc.z * inv, acc.w * inv);
    *(float4*)&g_feat[b][half * Hh + 4 * c] = m;

    // stats: dot(g,a), |g|^2, |a|^2 — pair halves via shared
    __shared__ float4 mbuf[256];
    mbuf[t] = m;
    __syncthreads();
    if (t < 128) {
        float4 mg = mbuf[t];
        float4 ma = mbuf[t + 128];
        float dot = mg.x * ma.x + mg.y * ma.y + mg.z * ma.z + mg.w * ma.w;
        float n2g = mg.x * mg.x + mg.y * mg.y + mg.z * mg.z + mg.w * mg.w;
        float n2a = ma.x * ma.x + ma.y * ma.y + ma.z * ma.z + ma.w * ma.w;
        __shared__ float red[3][4];
        int lane = t & 31, wid = t >> 5;
        #pragma unroll
        for (int o = 16; o > 0; o >>= 1) {
            dot += __shfl_down_sync(0xFFFFFFFFu, dot, o);
            n2g += __shfl_down_sync(0xFFFFFFFFu, n2g, o);
            n2a += __shfl_down_sync(0xFFFFFFFFu, n2a, o);
        }
        if (lane == 0) { red[0][wid] = dot; red[1][wid] = n2g; red[2][wid] = n2a; }
        __syncwarp();
        __syncthreads();
        if (t == 0) {
            g_stats[b][0] = red[0][0] + red[0][1] + red[0][2] + red[0][3];
            g_stats[b][1] = red[1][0] + red[1][1] + red[1][2] + red[1][3];
            g_stats[b][2] = red[2][0] + red[2][1] + red[2][2] + red[2][3];
        }
    }
}

// ---------------- 4) fused MLP (complexity features computed inline) ------------
__global__ void __launch_bounds__(256) k_mlp(
    const float* __restrict__ W1, const float* __restrict__ b1,
    const float* __restrict__ lng, const float* __restrict__ lnb,
    const float* __restrict__ W2, const float* __restrict__ b2,
    const float* __restrict__ W3, const float* __restrict__ b3)
{
    __shared__ float gs[RWS][GIN];      // input rows
    __shared__ float ts[RWS][Hh];       // post-LN+relu
    __shared__ float red[RWS][8];
    __shared__ float mu_s[RWS], rs_s[RWS];
    __shared__ float red3[8][RWS][2];
    __shared__ float raw_s[RWS][2];

    int t = threadIdx.x;                // 256 threads
    int row0 = blockIdx.x * RWS;
    int lane = t & 31, wid = t >> 5;

    // pooled means: 2H floats per row = 256 float4 per row
    for (int i = t; i < RWS * 256; i += 256) {
        int r = i >> 8, k = i & 255;
        *(float4*)&gs[r][4 * k] = *(const float4*)&g_feat[row0 + r][4 * k];
    }
    // complexity features inline (was k_complex)
    if (t < RWS) {
        int b = row0 + t;
        float cnt = (float)(g_off[b + 1] - g_off[b]);
        float ne  = (float)g_nedges[b];
        float scale   = logf(cnt + 1.f) * (1.f / logf(501.0f));
        float density = ne / (cnt * (cnt - 1.f) + 1e-8f);
        float avgdeg  = ne / (cnt + 1e-8f);
        float avn     = fminf(avgdeg * 0.1f, 1.f);
        float dot = g_stats[b][0], n2g = g_stats[b][1], n2a = g_stats[b][2];
        float na = fmaxf(sqrtf(n2g), 1e-8f);
        float nb = fmaxf(sqrtf(n2a), 1e-8f);
        float cosv = dot / (na * nb);
        gs[t][2 * Hh + 0] = scale;
        gs[t][2 * Hh + 1] = density;
        gs[t][2 * Hh + 2] = avn;
        gs[t][2 * Hh + 3] = (1.f - cosv) * 0.5f;
    }
    __syncthreads();

    // ---- layer 1: h = g @ W1 + b1 ; each thread owns cols 2t, 2t+1
    float2 acc[RWS];
    #pragma unroll
    for (int r = 0; r < RWS; r++) acc[r] = make_float2(0.f, 0.f);
    const float2* W1v = (const float2*)W1;  // W1[k][2t..2t+1] = W1v[k*256+t]
    for (int k = 0; k < GIN; k += 4) {
        float ga[RWS][4];
        #pragma unroll
        for (int r = 0; r < RWS; r++) {
            float4 q = *(const float4*)&gs[r][k];
            ga[r][0] = q.x; ga[r][1] = q.y; ga[r][2] = q.z; ga[r][3] = q.w;
        }
        #pragma unroll
        for (int kk = 0; kk < 4; kk++) {
            float2 w = W1v[(size_t)(k + kk) * 256 + t];
            #pragma unroll
            for (int r = 0; r < RWS; r++) {
                acc[r].x += ga[r][kk] * w.x;
                acc[r].y += ga[r][kk] * w.y;
            }
        }
    }
    float2 bb = ((const float2*)b1)[t];
    float2 h[RWS];
    #pragma unroll
    for (int r = 0; r < RWS; r++) { h[r].x = acc[r].x + bb.x; h[r].y = acc[r].y + bb.y; }

    // ---- layernorm (mean)
    #pragma unroll
    for (int r = 0; r < RWS; r++) {
        float p = h[r].x + h[r].y;
        #pragma unroll
        for (int o = 16; o > 0; o >>= 1) p += __shfl_down_sync(0xFFFFFFFFu, p, o);
        if (lane == 0) red[r][wid] = p;
    }
    __syncthreads();
    if (t < RWS) {
        float s = 0.f;
        #pragma unroll
        for (int w = 0; w < 8; w++) s += red[t][w];
        mu_s[t] = s * (1.f / (float)Hh);
    }
    __syncthreads();
    // ---- layernorm (var)
    #pragma unroll
    for (int r = 0; r < RWS; r++) {
        float dx = h[r].x - mu_s[r], dy = h[r].y - mu_s[r];
        float p = dx * dx + dy * dy;
        #pragma unroll
        for (int o = 16; o > 0; o >>= 1) p += __shfl_down_sync(0xFFFFFFFFu, p, o);
        if (lane == 0) red[r][wid] = p;
    }
    __syncthreads();
    if (t < RWS) {
        float s = 0.f;
        #pragma unroll
        for (int w = 0; w < 8; w++) s += red[t][w];
        rs_s[t] = rsqrtf(s * (1.f / (float)Hh) + 1e-5f);
    }
    __syncthreads();
    {
        float2 gv = ((const float2*)lng)[t];
        float2 bv = ((const float2*)lnb)[t];
        #pragma unroll
        for (int r = 0; r < RWS; r++) {
            float vx = (h[r].x - mu_s[r]) * rs_s[r] * gv.x + bv.x;
            float vy = (h[r].y - mu_s[r]) * rs_s[r] * gv.y + bv.y;
            ts[r][2 * t]     = fmaxf(vx, 0.f);
            ts[r][2 * t + 1] = fmaxf(vy, 0.f);
        }
    }
    __syncthreads();

    // ---- layer 2: u = relu(ts @ W2 + b2); thread t owns output col t (256 cols)
    float u[RWS];
    #pragma unroll
    for (int r = 0; r < RWS; r++) u[r] = 0.f;
    for (int k = 0; k < Hh; k += 4) {
        float ta[RWS][4];
        #pragma unroll
        for (int r = 0; r < RWS; r++) {
            float4 q = *(const float4*)&ts[r][k];
            ta[r][0] = q.x; ta[r][1] = q.y; ta[r][2] = q.z; ta[r][3] = q.w;
        }
        #pragma unroll
        for (int kk = 0; kk < 4; kk++) {
            float w = W2[(size_t)(k + kk) * 256 + t];
            #pragma unroll
            for (int r = 0; r < RWS; r++) u[r] += ta[r][kk] * w;
        }
    }
    float bt = b2[t];
    #pragma unroll
    for (int r = 0; r < RWS; r++) u[r] = fmaxf(u[r] + bt, 0.f);

    // ---- layer 3: raw[r][c] = sum_j u[r][j]*W3[j][c] + b3[c]
    float w30 = W3[2 * t], w31 = W3[2 * t + 1];
    float p0[RWS], p1[RWS];
    #pragma unroll
    for (int r = 0; r < RWS; r++) { p0[r] = u[r] * w30; p1[r] = u[r] * w31; }
    #pragma unroll
    for (int o = 16; o > 0; o >>= 1) {
        #pragma unroll
        for (int r = 0; r < RWS; r++) {
            p0[r] += __shfl_down_sync(0xFFFFFFFFu, p0[r], o);
            p1[r] += __shfl_down_sync(0xFFFFFFFFu, p1[r], o);
        }
    }
    if (lane == 0) {
        #pragma unroll
        for (int r = 0; r < RWS; r++) { red3[wid][r][0] = p0[r]; red3[wid][r][1] = p1[r]; }
    }
    __syncthreads();
    if (t < RWS * 2) {
        int r = t >> 1, c = t & 1;
        float s = 0.f;
        #pragma unroll
        for (int w = 0; w < 8; w++) s += red3[w][r][c];
        raw_s[r][c] = s + b3[c];
    }
    __syncthreads();
    if (t < RWS) {
        float r0 = raw_s[t][0], r1 = raw_s[t][1];
        float m = fmaxf(r0, r1);
        float e0 = expf(r0 - m), e1 = expf(r1 - m);
        float inv = 1.f / (e0 + e1);
        g_w[row0 + t][0] = e0 * inv;
        g_w[row0 + t][1] = e1 * inv;
    }
}

// ---------------- 5) gated fusion ----------------------------------------------
__global__ void __launch_bounds__(256) k_fuse(const float* __restrict__ xg,
                                              const float* __restrict__ xa,
                                              const int* __restrict__ batch,
                                              float* __restrict__ out) {
    size_t i = (size_t)blockIdx.x * blockDim.x + threadIdx.x;   // float4 index
    if (i >= (size_t)Nn * 128) return;
    int n = (int)(i >> 7);
    int b = __ldg(&batch[n]);
    float w0 = g_w[b][0], w1 = g_w[b][1];
    float4 g = ((const float4*)xg)[i];
    float4 a = ((const float4*)xa)[i];
    float4 o;
    o.x = w0 * g.x + w1 * a.x;
    o.y = w0 * g.y + w1 * a.y;
    o.z = w0 * g.z + w1 * a.z;
    o.w = w0 * g.w + w1 * a.w;
    ((float4*)out)[i] = o;
}

// ---------------- launch --------------------------------------------------------
extern "C" void kernel_launch(void* const* d_in, const int* in_sizes, int n_in,
                              void* d_out, int out_size) {
    const float* x_ggnn  = (const float*)d_in[0];
    const float* x_appnp = (const float*)d_in[1];
    const int*   edge    = (const int*)d_in[2];
    const int*   batch   = (const int*)d_in[3];
    const float* W1 = (const float*)d_in[4];
    const float* b1 = (const float*)d_in[5];
    const float* lng = (const float*)d_in[6];
    const float* lnb = (const float*)d_in[7];
    const float* W2 = (const float*)d_in[8];
    const float* b2 = (const float*)d_in[9];
    const float* W3 = (const float*)d_in[10];
    const float* b3 = (const float*)d_in[11];
    float* out = (float*)d_out;

    k_offsets<<<(Nn + 255) / 256, 256>>>(batch);
    k_edges<<<Ee / 4 / 256, 256>>>(edge, batch);
    k_pool<<<Bb, 256>>>(x_ggnn, x_appnp);
    k_mlp<<<Bb / RWS, 256>>>(W1, b1, lng, lnb, W2, b2, W3, b3);
    k_fuse<<<(Nn * 128 + 255) / 256, 256>>>(x_ggnn, x_appnp, batch, out);
}

// round 3
// speedup vs baseline: 1.4526x; 1.3342x over previous
#include <cuda_runtime.h>
#include <math.h>

#define Nn 100000
#define Ee 3200000
#define Hh 512
#define Bb 512
#define RWS 4      // rows per MLP block
#define BM 64
#define BN 32
#define BK 32
#define KK 1024    // GEMM1 K (pooled part only)
#define NC (KK / BK)

// ---------------- scratch (static device memory, no allocation) ----------------
__device__ int   g_off[Bb + 1];
__device__ int   g_nedges[Bb];
__device__ float g_poolT[KK][Bb];   // transposed pooled means: [feature][graph]
__device__ float g_h[Bb][Hh];       // GEMM1 output (pre-LN, missing rank-4 + b1)
__device__ float g_stats[Bb][3];    // dot, |g|^2, |a|^2 of pooled means
__device__ float g_w[Bb][2];        // softmax gate weights

// ---------------- 1) graph boundaries from sorted batch + zero nedges ----------
__global__ void k_offsets(const int* __restrict__ batch) {
    int i = blockIdx.x * blockDim.x + threadIdx.x;
    if (i < Bb) g_nedges[i] = 0;
    if (i >= Nn) return;
    int c = batch[i];
    int p = (i == 0) ? -1 : batch[i - 1];
    for (int b = p + 1; b <= c; b++) g_off[b] = i;
    if (i == Nn - 1) {
        for (int b = c + 1; b <= Bb; b++) g_off[b] = Nn;
    }
}

// ---------------- 2) same-graph edge histogram (int4-vectorized, one pass) -----
__global__ void __launch_bounds__(256) k_edges(const int* __restrict__ ei,
                                               const int* __restrict__ batch) {
    __shared__ int hist[Bb];
    for (int i = threadIdx.x; i < Bb; i += 256) hist[i] = 0;
    __syncthreads();
    const int4* src4 = (const int4*)ei;
    const int4* dst4 = (const int4*)(ei + Ee);
    int i = blockIdx.x * 256 + threadIdx.x;          // i < Ee/4 = 800000 exactly
    int4 s = __ldg(&src4[i]);
    int4 d = __ldg(&dst4[i]);
    int sg0 = __ldg(&batch[s.x]), sg1 = __ldg(&batch[s.y]);
    int sg2 = __ldg(&batch[s.z]), sg3 = __ldg(&batch[s.w]);
    int dg0 = __ldg(&batch[d.x]), dg1 = __ldg(&batch[d.y]);
    int dg2 = __ldg(&batch[d.z]), dg3 = __ldg(&batch[d.w]);
    if (sg0 == dg0) atomicAdd(&hist[sg0], 1);
    if (sg1 == dg1) atomicAdd(&hist[sg1], 1);
    if (sg2 == dg2) atomicAdd(&hist[sg2], 1);
    if (sg3 == dg3) atomicAdd(&hist[sg3], 1);
    __syncthreads();
    for (int b = threadIdx.x; b < Bb; b += 256) {
        int v = hist[b];
        if (v) atomicAdd(&g_nedges[b], v);
    }
}

// ---------------- 3) segment-mean pooling, transposed output --------------------
__global__ void __launch_bounds__(256) k_pool(const float* __restrict__ xg,
                                              const float* __restrict__ xa) {
    int b = blockIdx.x;
    int t = threadIdx.x;               // 256 threads
    int half = t >> 7;                 // 0 -> xg, 1 -> xa
    int c = t & 127;                   // float4 column within H
    int s0 = g_off[b], e0 = g_off[b + 1];

    const float4* p = ((const float4*)(half ? xa : xg)) + c;
    float4 acc = make_float4(0.f, 0.f, 0.f, 0.f);
    int r = s0;
    for (; r + 4 <= e0; r += 4) {
        float4 v0 = p[(size_t)(r + 0) * 128];
        float4 v1 = p[(size_t)(r + 1) * 128];
        float4 v2 = p[(size_t)(r + 2) * 128];
        float4 v3 = p[(size_t)(r + 3) * 128];
        acc.x += v0.x + v1.x + v2.x + v3.x;
        acc.y += v0.y + v1.y + v2.y + v3.y;
        acc.z += v0.z + v1.z + v2.z + v3.z;
        acc.w += v0.w + v1.w + v2.w + v3.w;
    }
    for (; r < e0; r++) {
        float4 v = p[(size_t)r * 128];
        acc.x += v.x; acc.y += v.y; acc.z += v.z; acc.w += v.w;
    }
    float inv = 1.f / fmaxf((float)(e0 - s0), 1.f);
    float4 m = make_float4(acc.x * inv, acc.y * inv, acc.z * inv, acc.w * inv);

    // transposed store: feature row = half*512 + 4c + j, column = b
    int kb = half * Hh + 4 * c;
    g_poolT[kb + 0][b] = m.x;
    g_poolT[kb + 1][b] = m.y;
    g_poolT[kb + 2][b] = m.z;
    g_poolT[kb + 3][b] = m.w;

    // stats: dot(g,a), |g|^2, |a|^2
    __shared__ float4 mbuf[256];
    __shared__ float red[3][4];
    mbuf[t] = m;
    __syncthreads();
    if (t < 128) {
        float4 mg = mbuf[t];
        float4 ma = mbuf[t + 128];
        float dot = mg.x * ma.x + mg.y * ma.y + mg.z * ma.z + mg.w * ma.w;
        float n2g = mg.x * mg.x + mg.y * mg.y + mg.z * mg.z + mg.w * mg.w;
        float n2a = ma.x * ma.x + ma.y * ma.y + ma.z * ma.z + ma.w * ma.w;
        int lane = t & 31, wid = t >> 5;
        #pragma unroll
        for (int o = 16; o > 0; o >>= 1) {
            dot += __shfl_down_sync(0xFFFFFFFFu, dot, o);
            n2g += __shfl_down_sync(0xFFFFFFFFu, n2g, o);
            n2a += __shfl_down_sync(0xFFFFFFFFu, n2a, o);
        }
        if (lane == 0) { red[0][wid] = dot; red[1][wid] = n2g; red[2][wid] = n2a; }
    }
    __syncthreads();
    if (t == 0) {
        g_stats[b][0] = red[0][0] + red[0][1] + red[0][2] + red[0][3];
        g_stats[b][1] = red[1][0] + red[1][1] + red[1][2] + red[1][3];
        g_stats[b][2] = red[2][0] + red[2][1] + red[2][2] + red[2][3];
    }
}

// ---------------- 4) GEMM1: g_h = poolT^T @ W1[0:1024]  (M=512,N=512,K=1024) ---
__global__ void __launch_bounds__(256) k_gemm1(const float* __restrict__ W1) {
    __shared__ float As[2][BK][BM];   // 16KB
    __shared__ float Ws[2][BK][BN];   // 8KB

    int t = threadIdx.x;
    int n0 = blockIdx.x * BN;
    int m0 = blockIdx.y * BM;
    int tn = t & 15;        // owns cols n0 + 2tn, 2tn+1
    int tm = t >> 4;        // owns rows m0 + 4tm .. 4tm+3

    // staging indices
    int ak = t >> 4;             // 0..15   (and ak+16)
    int af = t & 15;             // float4 slot along m
    int wk = t >> 3;             // 0..31
    int wq = t & 7;              // float4 slot along n

    const float* Abase = &g_poolT[0][0];
    size_t aIdx0 = (size_t)ak * Bb + m0 + 4 * af;
    size_t aIdx1 = (size_t)(ak + 16) * Bb + m0 + 4 * af;
    size_t wIdx  = (size_t)wk * Hh + n0 + 4 * wq;

    // load chunk 0
    *(float4*)&As[0][ak][4 * af]        = *(const float4*)&Abase[aIdx0];
    *(float4*)&As[0][ak + 16][4 * af]   = *(const float4*)&Abase[aIdx1];
    *(float4*)&Ws[0][wk][4 * wq]        = *(const float4*)&W1[wIdx];
    __syncthreads();

    float acc[4][2];
    #pragma unroll
    for (int j = 0; j < 4; j++) { acc[j][0] = 0.f; acc[j][1] = 0.f; }

    for (int c = 0; c < NC; c++) {
        int nb = c & 1;
        float4 ra0, ra1, rw;
        if (c + 1 < NC) {
            size_t koff = (size_t)(c + 1) * BK * Bb;
            size_t kwoff = (size_t)(c + 1) * BK * Hh;
            ra0 = *(const float4*)&Abase[koff + aIdx0];
            ra1 = *(const float4*)&Abase[koff + aIdx1];
            rw  = *(const float4*)&W1[kwoff + wIdx];
        }
        #pragma unroll
        for (int k = 0; k < BK; k++) {
            float4 a = *(float4*)&As[nb][k][4 * tm];
            float2 w = *(float2*)&Ws[nb][k][2 * tn];
            acc[0][0] += a.x * w.x; acc[0][1] += a.x * w.y;
            acc[1][0] += a.y * w.x; acc[1][1] += a.y * w.y;
            acc[2][0] += a.z * w.x; acc[2][1] += a.z * w.y;
            acc[3][0] += a.w * w.x; acc[3][1] += a.w * w.y;
        }
        if (c + 1 < NC) {
            __syncthreads();
            *(float4*)&As[1 - nb][ak][4 * af]      = ra0;
            *(float4*)&As[1 - nb][ak + 16][4 * af] = ra1;
            *(float4*)&Ws[1 - nb][wk][4 * wq]      = rw;
            __syncthreads();
        }
    }

    #pragma unroll
    for (int j = 0; j < 4; j++) {
        *(float2*)&g_h[m0 + 4 * tm + j][n0 + 2 * tn] = make_float2(acc[j][0], acc[j][1]);
    }
}

// ---------------- 5) MLP tail: rank-4 + b1 + LN + relu + GEMM2 + GEMM3 + softmax
__global__ void __launch_bounds__(256) k_mlp2(
    const float* __restrict__ W1, const float* __restrict__ b1,
    const float* __restrict__ lng, const float* __restrict__ lnb,
    const float* __restrict__ W2, const float* __restrict__ b2,
    const float* __restrict__ W3, const float* __restrict__ b3)
{
    __shared__ float comp[RWS][4];
    __shared__ float ts[RWS][Hh];       // post-LN+relu
    __shared__ float red[RWS][8];
    __shared__ float mu_s[RWS], rs_s[RWS];
    __shared__ float red3[8][RWS][2];
    __shared__ float raw_s[RWS][2];

    int t = threadIdx.x;                // 256 threads
    int row0 = blockIdx.x * RWS;
    int lane = t & 31, wid = t >> 5;

    // complexity features
    if (t < RWS) {
        int b = row0 + t;
        float cnt = (float)(g_off[b + 1] - g_off[b]);
        float ne  = (float)g_nedges[b];
        float scale   = logf(cnt + 1.f) * (1.f / logf(501.0f));
        float density = ne / (cnt * (cnt - 1.f) + 1e-8f);
        float avgdeg  = ne / (cnt + 1e-8f);
        float avn     = fminf(avgdeg * 0.1f, 1.f);
        float dot = g_stats[b][0], n2g = g_stats[b][1], n2a = g_stats[b][2];
        float na = fmaxf(sqrtf(n2g), 1e-8f);
        float nb = fmaxf(sqrtf(n2a), 1e-8f);
        float cosv = dot / (na * nb);
        comp[t][0] = scale;
        comp[t][1] = density;
        comp[t][2] = avn;
        comp[t][3] = (1.f - cosv) * 0.5f;
    }
    __syncthreads();

    // h = g_h + comp @ W1[1024:1028] + b1  ; thread owns cols 2t, 2t+1
    float2 w1t[4];
    #pragma unroll
    for (int j = 0; j < 4; j++)
        w1t[j] = *(const float2*)&W1[(size_t)(KK + j) * Hh + 2 * t];
    float2 bb = ((const float2*)b1)[t];
    float2 h[RWS];
    #pragma unroll
    for (int r = 0; r < RWS; r++) {
        float2 hg = *(const float2*)&g_h[row0 + r][2 * t];
        float hx = hg.x + bb.x, hy = hg.y + bb.y;
        #pragma unroll
        for (int j = 0; j < 4; j++) {
            hx += comp[r][j] * w1t[j].x;
            hy += comp[r][j] * w1t[j].y;
        }
        h[r] = make_float2(hx, hy);
    }

    // layernorm mean
    #pragma unroll
    for (int r = 0; r < RWS; r++) {
        float p = h[r].x + h[r].y;
        #pragma unroll
        for (int o = 16; o > 0; o >>= 1) p += __shfl_down_sync(0xFFFFFFFFu, p, o);
        if (lane == 0) red[r][wid] = p;
    }
    __syncthreads();
    if (t < RWS) {
        float s = 0.f;
        #pragma unroll
        for (int w = 0; w < 8; w++) s += red[t][w];
        mu_s[t] = s * (1.f / (float)Hh);
    }
    __syncthreads();
    // layernorm var
    #pragma unroll
    for (int r = 0; r < RWS; r++) {
        float dx = h[r].x - mu_s[r], dy = h[r].y - mu_s[r];
        float p = dx * dx + dy * dy;
        #pragma unroll
        for (int o = 16; o > 0; o >>= 1) p += __shfl_down_sync(0xFFFFFFFFu, p, o);
        if (lane == 0) red[r][wid] = p;
    }
    __syncthreads();
    if (t < RWS) {
        float s = 0.f;
        #pragma unroll
        for (int w = 0; w < 8; w++) s += red[t][w];
        rs_s[t] = rsqrtf(s * (1.f / (float)Hh) + 1e-5f);
    }
    __syncthreads();
    {
        float2 gv = ((const float2*)lng)[t];
        float2 bv = ((const float2*)lnb)[t];
        #pragma unroll
        for (int r = 0; r < RWS; r++) {
            float vx = (h[r].x - mu_s[r]) * rs_s[r] * gv.x + bv.x;
            float vy = (h[r].y - mu_s[r]) * rs_s[r] * gv.y + bv.y;
            ts[r][2 * t]     = fmaxf(vx, 0.f);
            ts[r][2 * t + 1] = fmaxf(vy, 0.f);
        }
    }
    __syncthreads();

    // GEMM2: u = relu(ts @ W2 + b2); thread owns col t; prefetched weights
    float u[RWS];
    #pragma unroll
    for (int r = 0; r < RWS; r++) u[r] = 0.f;
    float wr[4];
    #pragma unroll
    for (int j = 0; j < 4; j++) wr[j] = W2[(size_t)j * 256 + t];
    for (int k = 0; k < Hh; k += 4) {
        float wn[4];
        if (k + 4 < Hh) {
            #pragma unroll
            for (int j = 0; j < 4; j++) wn[j] = W2[(size_t)(k + 4 + j) * 256 + t];
        }
        float ta[RWS][4];
        #pragma unroll
        for (int r = 0; r < RWS; r++) {
            float4 q = *(const float4*)&ts[r][k];
            ta[r][0] = q.x; ta[r][1] = q.y; ta[r][2] = q.z; ta[r][3] = q.w;
        }
        #pragma unroll
        for (int kk = 0; kk < 4; kk++) {
            #pragma unroll
            for (int r = 0; r < RWS; r++) u[r] += ta[r][kk] * wr[kk];
        }
        #pragma unroll
        for (int j = 0; j < 4; j++) wr[j] = wn[j];
    }
    float bt = b2[t];
    #pragma unroll
    for (int r = 0; r < RWS; r++) u[r] = fmaxf(u[r] + bt, 0.f);

    // GEMM3: raw[r][c] = sum_j u[r][j]*W3[j][c] + b3[c]
    float w30 = W3[2 * t], w31 = W3[2 * t + 1];
    float p0[RWS], p1[RWS];
    #pragma unroll
    for (int r = 0; r < RWS; r++) { p0[r] = u[r] * w30; p1[r] = u[r] * w31; }
    #pragma unroll
    for (int o = 16; o > 0; o >>= 1) {
        #pragma unroll
        for (int r = 0; r < RWS; r++) {
            p0[r] += __shfl_down_sync(0xFFFFFFFFu, p0[r], o);
            p1[r] += __shfl_down_sync(0xFFFFFFFFu, p1[r], o);
        }
    }
    if (lane == 0) {
        #pragma unroll
        for (int r = 0; r < RWS; r++) { red3[wid][r][0] = p0[r]; red3[wid][r][1] = p1[r]; }
    }
    __syncthreads();
    if (t < RWS * 2) {
        int r = t >> 1, c = t & 1;
        float s = 0.f;
        #pragma unroll
        for (int w = 0; w < 8; w++) s += red3[w][r][c];
        raw_s[r][c] = s + b3[c];
    }
    __syncthreads();
    if (t < RWS) {
        float r0 = raw_s[t][0], r1 = raw_s[t][1];
        float m = fmaxf(r0, r1);
        float e0 = expf(r0 - m), e1 = expf(r1 - m);
        float inv = 1.f / (e0 + e1);
        g_w[row0 + t][0] = e0 * inv;
        g_w[row0 + t][1] = e1 * inv;
    }
}

// ---------------- 6) gated fusion (streaming) -----------------------------------
__global__ void __launch_bounds__(256) k_fuse(const float* __restrict__ xg,
                                              const float* __restrict__ xa,
                                              const int* __restrict__ batch,
                                              float* __restrict__ out) {
    size_t i = (size_t)blockIdx.x * blockDim.x + threadIdx.x;   // float4 index
    if (i >= (size_t)Nn * 128) return;
    int n = (int)(i >> 7);
    int b = __ldg(&batch[n]);
    float w0 = g_w[b][0], w1 = g_w[b][1];
    float4 g = __ldcs(((const float4*)xg) + i);
    float4 a = __ldcs(((const float4*)xa) + i);
    float4 o;
    o.x = w0 * g.x + w1 * a.x;
    o.y = w0 * g.y + w1 * a.y;
    o.z = w0 * g.z + w1 * a.z;
    o.w = w0 * g.w + w1 * a.w;
    __stcs(((float4*)out) + i, o);
}

// ---------------- launch --------------------------------------------------------
extern "C" void kernel_launch(void* const* d_in, const int* in_sizes, int n_in,
                              void* d_out, int out_size) {
    const float* x_ggnn  = (const float*)d_in[0];
    const float* x_appnp = (const float*)d_in[1];
    const int*   edge    = (const int*)d_in[2];
    const int*   batch   = (const int*)d_in[3];
    const float* W1 = (const float*)d_in[4];
    const float* b1 = (const float*)d_in[5];
    const float* lng = (const float*)d_in[6];
    const float* lnb = (const float*)d_in[7];
    const float* W2 = (const float*)d_in[8];
    const float* b2 = (const float*)d_in[9];
    const float* W3 = (const float*)d_in[10];
    const float* b3 = (const float*)d_in[11];
    float* out = (float*)d_out;

    k_offsets<<<(Nn + 255) / 256, 256>>>(batch);
    k_edges<<<Ee / 4 / 256, 256>>>(edge, batch);
    k_pool<<<Bb, 256>>>(x_ggnn, x_appnp);
    k_gemm1<<<dim3(Hh / BN, Bb / BM), 256>>>(W1);
    k_mlp2<<<Bb / RWS, 256>>>(W1, b1, lng, lnb, W2, b2, W3, b3);
    k_fuse<<<(Nn * 128 + 255) / 256, 256>>>(x_ggnn, x_appnp, batch, out);
}

// round 4
// speedup vs baseline: 1.6276x; 1.1205x over previous
#include <cuda_runtime.h>
#include <math.h>

#define Nn 100000
#define Ee 3200000
#define Hh 512
#define Bb 512
#define RWS 4      // rows per MLP block
#define BM 64
#define BN 32
#define BK 32
#define KK 1024    // GEMM1 K (pooled part only)
#define KHALF 512
#define NCH (KHALF / BK)   // 16 chunks per K-half

// ---------------- scratch (static device memory, no allocation) ----------------
__device__ int   g_off[Bb + 1];
__device__ int   g_nedges[Bb];
__device__ float g_poolT[KK][Bb];     // transposed pooled means: [feature][graph]
__device__ float g_hp[2][Bb][Hh];     // split-K GEMM1 partial outputs
__device__ float g_stats[Bb][3];      // dot, |g|^2, |a|^2 of pooled means
__device__ float g_w[Bb][2];          // softmax gate weights

// ---------------- streams/events for fork-join (host-side, static init) --------
static cudaStream_t sA = 0, sB = 0;
static cudaEvent_t evRoot = 0, evA = 0, evB = 0;
static bool s_ok = false;
struct StreamInit {
    StreamInit() {
        bool ok = true;
        ok &= cudaStreamCreateWithFlags(&sA, cudaStreamNonBlocking) == cudaSuccess;
        ok &= cudaStreamCreateWithFlags(&sB, cudaStreamNonBlocking) == cudaSuccess;
        ok &= cudaEventCreateWithFlags(&evRoot, cudaEventDisableTiming) == cudaSuccess;
        ok &= cudaEventCreateWithFlags(&evA, cudaEventDisableTiming) == cudaSuccess;
        ok &= cudaEventCreateWithFlags(&evB, cudaEventDisableTiming) == cudaSuccess;
        s_ok = ok;
    }
};
static StreamInit s_init;

// ---------------- 0) zero nedges ------------------------------------------------
__global__ void k_zero() { g_nedges[threadIdx.x] = 0; }

// ---------------- 1) graph boundaries from sorted batch -------------------------
__global__ void k_offsets(const int* __restrict__ batch) {
    int i = blockIdx.x * blockDim.x + threadIdx.x;
    if (i >= Nn) return;
    int c = batch[i];
    int p = (i == 0) ? -1 : batch[i - 1];
    for (int b = p + 1; b <= c; b++) g_off[b] = i;
    if (i == Nn - 1) {
        for (int b = c + 1; b <= Bb; b++) g_off[b] = Nn;
    }
}

// ---------------- 2) same-graph edge histogram (int4-vectorized, one pass) -----
__global__ void __launch_bounds__(256) k_edges(const int* __restrict__ ei,
                                               const int* __restrict__ batch) {
    __shared__ int hist[Bb];
    for (int i = threadIdx.x; i < Bb; i += 256) hist[i] = 0;
    __syncthreads();
    const int4* src4 = (const int4*)ei;
    const int4* dst4 = (const int4*)(ei + Ee);
    int i = blockIdx.x * 256 + threadIdx.x;          // i < Ee/4 = 800000 exactly
    int4 s = __ldg(&src4[i]);
    int4 d = __ldg(&dst4[i]);
    int sg0 = __ldg(&batch[s.x]), sg1 = __ldg(&batch[s.y]);
    int sg2 = __ldg(&batch[s.z]), sg3 = __ldg(&batch[s.w]);
    int dg0 = __ldg(&batch[d.x]), dg1 = __ldg(&batch[d.y]);
    int dg2 = __ldg(&batch[d.z]), dg3 = __ldg(&batch[d.w]);
    if (sg0 == dg0) atomicAdd(&hist[sg0], 1);
    if (sg1 == dg1) atomicAdd(&hist[sg1], 1);
    if (sg2 == dg2) atomicAdd(&hist[sg2], 1);
    if (sg3 == dg3) atomicAdd(&hist[sg3], 1);
    __syncthreads();
    for (int b = threadIdx.x; b < Bb; b += 256) {
        int v = hist[b];
        if (v) atomicAdd(&g_nedges[b], v);
    }
}

// ---------------- 3) segment-mean pooling (binary-search range, transposed out)
__device__ __forceinline__ int lbound(const int* __restrict__ batch, int key) {
    int lo = 0, hi = Nn;
    while (lo < hi) {
        int mid = (lo + hi) >> 1;
        if (batch[mid] < key) lo = mid + 1; else hi = mid;
    }
    return lo;
}

__global__ void __launch_bounds__(256) k_pool(const float* __restrict__ xg,
                                              const float* __restrict__ xa,
                                              const int* __restrict__ batch) {
    int b = blockIdx.x;
    int t = threadIdx.x;               // 256 threads
    int half = t >> 7;                 // 0 -> xg, 1 -> xa
    int c = t & 127;                   // float4 column within H
    int s0 = lbound(batch, b);
    int e0 = lbound(batch, b + 1);

    const float4* p = ((const float4*)(half ? xa : xg)) + c;
    float4 acc = make_float4(0.f, 0.f, 0.f, 0.f);
    int r = s0;
    for (; r + 4 <= e0; r += 4) {
        float4 v0 = __ldcs(&p[(size_t)(r + 0) * 128]);
        float4 v1 = __ldcs(&p[(size_t)(r + 1) * 128]);
        float4 v2 = __ldcs(&p[(size_t)(r + 2) * 128]);
        float4 v3 = __ldcs(&p[(size_t)(r + 3) * 128]);
        acc.x += v0.x + v1.x + v2.x + v3.x;
        acc.y += v0.y + v1.y + v2.y + v3.y;
        acc.z += v0.z + v1.z + v2.z + v3.z;
        acc.w += v0.w + v1.w + v2.w + v3.w;
    }
    for (; r < e0; r++) {
        float4 v = __ldcs(&p[(size_t)r * 128]);
        acc.x += v.x; acc.y += v.y; acc.z += v.z; acc.w += v.w;
    }
    float inv = 1.f / fmaxf((float)(e0 - s0), 1.f);
    float4 m = make_float4(acc.x * inv, acc.y * inv, acc.z * inv, acc.w * inv);

    // transposed store: feature row = half*512 + 4c + j, column = b
    int kb = half * Hh + 4 * c;
    g_poolT[kb + 0][b] = m.x;
    g_poolT[kb + 1][b] = m.y;
    g_poolT[kb + 2][b] = m.z;
    g_poolT[kb + 3][b] = m.w;

    // stats: dot(g,a), |g|^2, |a|^2
    __shared__ float4 mbuf[256];
    __shared__ float red[3][4];
    mbuf[t] = m;
    __syncthreads();
    if (t < 128) {
        float4 mg = mbuf[t];
        float4 ma = mbuf[t + 128];
        float dot = mg.x * ma.x + mg.y * ma.y + mg.z * ma.z + mg.w * ma.w;
        float n2g = mg.x * mg.x + mg.y * mg.y + mg.z * mg.z + mg.w * mg.w;
        float n2a = ma.x * ma.x + ma.y * ma.y + ma.z * ma.z + ma.w * ma.w;
        int lane = t & 31, wid = t >> 5;
        #pragma unroll
        for (int o = 16; o > 0; o >>= 1) {
            dot += __shfl_down_sync(0xFFFFFFFFu, dot, o);
            n2g += __shfl_down_sync(0xFFFFFFFFu, n2g, o);
            n2a += __shfl_down_sync(0xFFFFFFFFu, n2a, o);
        }
        if (lane == 0) { red[0][wid] = dot; red[1][wid] = n2g; red[2][wid] = n2a; }
    }
    __syncthreads();
    if (t == 0) {
        g_stats[b][0] = red[0][0] + red[0][1] + red[0][2] + red[0][3];
        g_stats[b][1] = red[1][0] + red[1][1] + red[1][2] + red[1][3];
        g_stats[b][2] = red[2][0] + red[2][1] + red[2][2] + red[2][3];
    }
}

// ---------------- 4) GEMM1 split-K=2: g_hp[z] = poolT[zK:]^T @ W1[zK:] ---------
__global__ void __launch_bounds__(256) k_gemm1(const float* __restrict__ W1) {
    __shared__ float As[2][BK][BM];   // 16KB
    __shared__ float Ws[2][BK][BN];   // 8KB

    int t = threadIdx.x;
    int n0 = blockIdx.x * BN;
    int m0 = blockIdx.y * BM;
    int z  = blockIdx.z;
    int tn = t & 15;        // owns cols n0 + 2tn, 2tn+1
    int tm = t >> 4;        // owns rows m0 + 4tm .. 4tm+3

    // staging indices
    int ak = t >> 4;             // 0..15   (and ak+16)
    int af = t & 15;             // float4 slot along m
    int wk = t >> 3;             // 0..31
    int wq = t & 7;              // float4 slot along n

    const float* Abase = &g_poolT[z * KHALF][0];
    const float* Wbase = W1 + (size_t)z * KHALF * Hh;
    size_t aIdx0 = (size_t)ak * Bb + m0 + 4 * af;
    size_t aIdx1 = (size_t)(ak + 16) * Bb + m0 + 4 * af;
    size_t wIdx  = (size_t)wk * Hh + n0 + 4 * wq;

    // load chunk 0
    *(float4*)&As[0][ak][4 * af]        = *(const float4*)&Abase[aIdx0];
    *(float4*)&As[0][ak + 16][4 * af]   = *(const float4*)&Abase[aIdx1];
    *(float4*)&Ws[0][wk][4 * wq]        = *(const float4*)&Wbase[wIdx];
    __syncthreads();

    float acc[4][2];
    #pragma unroll
    for (int j = 0; j < 4; j++) { acc[j][0] = 0.f; acc[j][1] = 0.f; }

    for (int c = 0; c < NCH; c++) {
        int nb = c & 1;
        float4 ra0, ra1, rw;
        if (c + 1 < NCH) {
            size_t koff  = (size_t)(c + 1) * BK * Bb;
            size_t kwoff = (size_t)(c + 1) * BK * Hh;
            ra0 = *(const float4*)&Abase[koff + aIdx0];
            ra1 = *(const float4*)&Abase[koff + aIdx1];
            rw  = *(const float4*)&Wbase[kwoff + wIdx];
        }
        #pragma unroll
        for (int k = 0; k < BK; k++) {
            float4 a = *(float4*)&As[nb][k][4 * tm];
            float2 w = *(float2*)&Ws[nb][k][2 * tn];
            acc[0][0] += a.x * w.x; acc[0][1] += a.x * w.y;
            acc[1][0] += a.y * w.x; acc[1][1] += a.y * w.y;
            acc[2][0] += a.z * w.x; acc[2][1] += a.z * w.y;
            acc[3][0] += a.w * w.x; acc[3][1] += a.w * w.y;
        }
        if (c + 1 < NCH) {
            __syncthreads();
            *(float4*)&As[1 - nb][ak][4 * af]      = ra0;
            *(float4*)&As[1 - nb][ak + 16][4 * af] = ra1;
            *(float4*)&Ws[1 - nb][wk][4 * wq]      = rw;
            __syncthreads();
        }
    }

    #pragma unroll
    for (int j = 0; j < 4; j++) {
        *(float2*)&g_hp[z][m0 + 4 * tm + j][n0 + 2 * tn] = make_float2(acc[j][0], acc[j][1]);
    }
}

// ---------------- 5) MLP tail: rank-4 + b1 + LN + relu + GEMM2 + GEMM3 + softmax
__global__ void __launch_bounds__(256) k_mlp2(
    const float* __restrict__ W1, const float* __restrict__ b1,
    const float* __restrict__ lng, const float* __restrict__ lnb,
    const float* __restrict__ W2, const float* __restrict__ b2,
    const float* __restrict__ W3, const float* __restrict__ b3)
{
    __shared__ float comp[RWS][4];
    __shared__ float ts[RWS][Hh];       // post-LN+relu
    __shared__ float red[RWS][8];
    __shared__ float mu_s[RWS], rs_s[RWS];
    __shared__ float red3[8][RWS][2];
    __shared__ float raw_s[RWS][2];

    int t = threadIdx.x;                // 256 threads
    int row0 = blockIdx.x * RWS;
    int lane = t & 31, wid = t >> 5;

    // complexity features
    if (t < RWS) {
        int b = row0 + t;
        float cnt = (float)(g_off[b + 1] - g_off[b]);
        float ne  = (float)g_nedges[b];
        float scale   = logf(cnt + 1.f) * (1.f / logf(501.0f));
        float density = ne / (cnt * (cnt - 1.f) + 1e-8f);
        float avgdeg  = ne / (cnt + 1e-8f);
        float avn     = fminf(avgdeg * 0.1f, 1.f);
        float dot = g_stats[b][0], n2g = g_stats[b][1], n2a = g_stats[b][2];
        float na = fmaxf(sqrtf(n2g), 1e-8f);
        float nb = fmaxf(sqrtf(n2a), 1e-8f);
        float cosv = dot / (na * nb);
        comp[t][0] = scale;
        comp[t][1] = density;
        comp[t][2] = avn;
        comp[t][3] = (1.f - cosv) * 0.5f;
    }
    __syncthreads();

    // h = g_hp[0] + g_hp[1] + comp @ W1[1024:1028] + b1 ; thread owns cols 2t,2t+1
    float2 w1t[4];
    #pragma unroll
    for (int j = 0; j < 4; j++)
        w1t[j] = *(const float2*)&W1[(size_t)(KK + j) * Hh + 2 * t];
    float2 bb = ((const float2*)b1)[t];
    float2 h[RWS];
    #pragma unroll
    for (int r = 0; r < RWS; r++) {
        float2 hg0 = *(const float2*)&g_hp[0][row0 + r][2 * t];
        float2 hg1 = *(const float2*)&g_hp[1][row0 + r][2 * t];
        float hx = hg0.x + hg1.x + bb.x, hy = hg0.y + hg1.y + bb.y;
        #pragma unroll
        for (int j = 0; j < 4; j++) {
            hx += comp[r][j] * w1t[j].x;
            hy += comp[r][j] * w1t[j].y;
        }
        h[r] = make_float2(hx, hy);
    }

    // layernorm mean
    #pragma unroll
    for (int r = 0; r < RWS; r++) {
        float p = h[r].x + h[r].y;
        #pragma unroll
        for (int o = 16; o > 0; o >>= 1) p += __shfl_down_sync(0xFFFFFFFFu, p, o);
        if (lane == 0) red[r][wid] = p;
    }
    __syncthreads();
    if (t < RWS) {
        float s = 0.f;
        #pragma unroll
        for (int w = 0; w < 8; w++) s += red[t][w];
        mu_s[t] = s * (1.f / (float)Hh);
    }
    __syncthreads();
    // layernorm var
    #pragma unroll
    for (int r = 0; r < RWS; r++) {
        float dx = h[r].x - mu_s[r], dy = h[r].y - mu_s[r];
        float p = dx * dx + dy * dy;
        #pragma unroll
        for (int o = 16; o > 0; o >>= 1) p += __shfl_down_sync(0xFFFFFFFFu, p, o);
        if (lane == 0) red[r][wid] = p;
    }
    __syncthreads();
    if (t < RWS) {
        float s = 0.f;
        #pragma unroll
        for (int w = 0; w < 8; w++) s += red[t][w];
        rs_s[t] = rsqrtf(s * (1.f / (float)Hh) + 1e-5f);
    }
    __syncthreads();
    {
        float2 gv = ((const float2*)lng)[t];
        float2 bv = ((const float2*)lnb)[t];
        #pragma unroll
        for (int r = 0; r < RWS; r++) {
            float vx = (h[r].x - mu_s[r]) * rs_s[r] * gv.x + bv.x;
            float vy = (h[r].y - mu_s[r]) * rs_s[r] * gv.y + bv.y;
            ts[r][2 * t]     = fmaxf(vx, 0.f);
            ts[r][2 * t + 1] = fmaxf(vy, 0.f);
        }
    }
    __syncthreads();

    // GEMM2: u = relu(ts @ W2 + b2); thread owns col t; prefetched weights
    float u[RWS];
    #pragma unroll
    for (int r = 0; r < RWS; r++) u[r] = 0.f;
    float wr[4];
    #pragma unroll
    for (int j = 0; j < 4; j++) wr[j] = W2[(size_t)j * 256 + t];
    for (int k = 0; k < Hh; k += 4) {
        float wn[4];
        if (k + 4 < Hh) {
            #pragma unroll
            for (int j = 0; j < 4; j++) wn[j] = W2[(size_t)(k + 4 + j) * 256 + t];
        }
        float ta[RWS][4];
        #pragma unroll
        for (int r = 0; r < RWS; r++) {
            float4 q = *(const float4*)&ts[r][k];
            ta[r][0] = q.x; ta[r][1] = q.y; ta[r][2] = q.z; ta[r][3] = q.w;
        }
        #pragma unroll
        for (int kk = 0; kk < 4; kk++) {
            #pragma unroll
            for (int r = 0; r < RWS; r++) u[r] += ta[r][kk] * wr[kk];
        }
        #pragma unroll
        for (int j = 0; j < 4; j++) wr[j] = wn[j];
    }
    float bt = b2[t];
    #pragma unroll
    for (int r = 0; r < RWS; r++) u[r] = fmaxf(u[r] + bt, 0.f);

    // GEMM3: raw[r][c] = sum_j u[r][j]*W3[j][c] + b3[c]
    float w30 = W3[2 * t], w31 = W3[2 * t + 1];
    float p0[RWS], p1[RWS];
    #pragma unroll
    for (int r = 0; r < RWS; r++) { p0[r] = u[r] * w30; p1[r] = u[r] * w31; }
    #pragma unroll
    for (int o = 16; o > 0; o >>= 1) {
        #pragma unroll
        for (int r = 0; r < RWS; r++) {
            p0[r] += __shfl_down_sync(0xFFFFFFFFu, p0[r], o);
            p1[r] += __shfl_down_sync(0xFFFFFFFFu, p1[r], o);
        }
    }
    if (lane == 0) {
        #pragma unroll
        for (int r = 0; r < RWS; r++) { red3[wid][r][0] = p0[r]; red3[wid][r][1] = p1[r]; }
    }
    __syncthreads();
    if (t < RWS * 2) {
        int r = t >> 1, c = t & 1;
        float s = 0.f;
        #pragma unroll
        for (int w = 0; w < 8; w++) s += red3[w][r][c];
        raw_s[r][c] = s + b3[c];
    }
    __syncthreads();
    if (t < RWS) {
        float r0 = raw_s[t][0], r1 = raw_s[t][1];
        float m = fmaxf(r0, r1);
        float e0 = expf(r0 - m), e1 = expf(r1 - m);
        float inv = 1.f / (e0 + e1);
        g_w[row0 + t][0] = e0 * inv;
        g_w[row0 + t][1] = e1 * inv;
    }
}

// ---------------- 6) gated fusion (streaming) -----------------------------------
__global__ void __launch_bounds__(256) k_fuse(const float* __restrict__ xg,
                                              const float* __restrict__ xa,
                                              const int* __restrict__ batch,
                                              float* __restrict__ out) {
    size_t i = (size_t)blockIdx.x * blockDim.x + threadIdx.x;   // float4 index
    if (i >= (size_t)Nn * 128) return;
    int n = (int)(i >> 7);
    int b = __ldg(&batch[n]);
    float w0 = g_w[b][0], w1 = g_w[b][1];
    float4 g = __ldcs(((const float4*)xg) + i);
    float4 a = __ldcs(((const float4*)xa) + i);
    float4 o;
    o.x = w0 * g.x + w1 * a.x;
    o.y = w0 * g.y + w1 * a.y;
    o.z = w0 * g.z + w1 * a.z;
    o.w = w0 * g.w + w1 * a.w;
    __stcs(((float4*)out) + i, o);
}

// ---------------- launch --------------------------------------------------------
extern "C" void kernel_launch(void* const* d_in, const int* in_sizes, int n_in,
                              void* d_out, int out_size) {
    const float* x_ggnn  = (const float*)d_in[0];
    const float* x_appnp = (const float*)d_in[1];
    const int*   edge    = (const int*)d_in[2];
    const int*   batch   = (const int*)d_in[3];
    const float* W1 = (const float*)d_in[4];
    const float* b1 = (const float*)d_in[5];
    const float* lng = (const float*)d_in[6];
    const float* lnb = (const float*)d_in[7];
    const float* W2 = (const float*)d_in[8];
    const float* b2 = (const float*)d_in[9];
    const float* W3 = (const float*)d_in[10];
    const float* b3 = (const float*)d_in[11];
    float* out = (float*)d_out;

    if (s_ok) {
        // fork: side work that only feeds k_mlp2
        cudaEventRecord(evRoot, 0);
        cudaStreamWaitEvent(sA, evRoot, 0);
        k_zero<<<1, Bb, 0, sA>>>();
        k_edges<<<Ee / 4 / 256, 256, 0, sA>>>(edge, batch);
        cudaEventRecord(evA, sA);
        cudaStreamWaitEvent(sB, evRoot, 0);
        k_offsets<<<(Nn + 255) / 256, 256, 0, sB>>>(batch);
        cudaEventRecord(evB, sB);

        // main critical path
        k_pool<<<Bb, 256>>>(x_ggnn, x_appnp, batch);
        k_gemm1<<<dim3(Hh / BN, Bb / BM, 2), 256>>>(W1);
        cudaStreamWaitEvent(0, evA, 0);
        cudaStreamWaitEvent(0, evB, 0);
        k_mlp2<<<Bb / RWS, 256>>>(W1, b1, lng, lnb, W2, b2, W3, b3);
        k_fuse<<<(Nn * 128 + 255) / 256, 256>>>(x_ggnn, x_appnp, batch, out);
    } else {
        // serial fallback
        k_zero<<<1, Bb>>>();
        k_edges<<<Ee / 4 / 256, 256>>>(edge, batch);
        k_offsets<<<(Nn + 255) / 256, 256>>>(batch);
        k_pool<<<Bb, 256>>>(x_ggnn, x_appnp, batch);
        k_gemm1<<<dim3(Hh / BN, Bb / BM, 2), 256>>>(W1);
        k_mlp2<<<Bb / RWS, 256>>>(W1, b1, lng, lnb, W2, b2, W3, b3);
        k_fuse<<<(Nn * 128 + 255) / 256, 256>>>(x_ggnn, x_appnp, batch, out);
    }
}

// round 5
// speedup vs baseline: 1.7494x; 1.0748x over previous
#include <cuda_runtime.h>
#include <math.h>

#define Nn 100000
#define Ee 3200000
#define Hh 512
#define Bb 512
#define RWS 4      // rows per MLP block
#define BM 64
#define BN 32
#define BK 32
#define KK 1024    // GEMM1 K (pooled part only)
#define KHALF 512
#define NCH (KHALF / BK)   // 16 chunks per K-half

// ---------------- scratch (static device memory, no allocation) ----------------
__device__ int   g_off[Bb + 1];
__device__ int   g_nedges[Bb];
__device__ float g_poolT[KK][Bb];     // transposed pooled means: [feature][graph]
__device__ float g_pool[Bb][KK];      // row-major pooled means (for stats)
__device__ float g_hp[2][Bb][Hh];     // split-K GEMM1 partial outputs
__device__ float g_w[Bb][2];          // softmax gate weights

// ---------------- streams/events for fork-join (host-side, static init) --------
static cudaStream_t sA = 0, sB = 0;
static cudaEvent_t evRoot = 0, evA = 0, evB = 0;
static bool s_ok = false;
struct StreamInit {
    StreamInit() {
        bool ok = true;
        ok &= cudaStreamCreateWithFlags(&sA, cudaStreamNonBlocking) == cudaSuccess;
        ok &= cudaStreamCreateWithFlags(&sB, cudaStreamNonBlocking) == cudaSuccess;
        ok &= cudaEventCreateWithFlags(&evRoot, cudaEventDisableTiming) == cudaSuccess;
        ok &= cudaEventCreateWithFlags(&evA, cudaEventDisableTiming) == cudaSuccess;
        ok &= cudaEventCreateWithFlags(&evB, cudaEventDisableTiming) == cudaSuccess;
        s_ok = ok;
    }
};
static StreamInit s_init;

// ---------------- 0) zero nedges ------------------------------------------------
__global__ void k_zero() { g_nedges[threadIdx.x] = 0; }

// ---------------- 1) graph boundaries from sorted batch -------------------------
__global__ void k_offsets(const int* __restrict__ batch) {
    int i = blockIdx.x * blockDim.x + threadIdx.x;
    if (i >= Nn) return;
    int c = batch[i];
    int p = (i == 0) ? -1 : batch[i - 1];
    for (int b = p + 1; b <= c; b++) g_off[b] = i;
    if (i == Nn - 1) {
        for (int b = c + 1; b <= Bb; b++) g_off[b] = Nn;
    }
}

// ---------------- 2) same-graph edge histogram (int4-vectorized, one pass) -----
__global__ void __launch_bounds__(256) k_edges(const int* __restrict__ ei,
                                               const int* __restrict__ batch) {
    __shared__ int hist[Bb];
    for (int i = threadIdx.x; i < Bb; i += 256) hist[i] = 0;
    __syncthreads();
    const int4* src4 = (const int4*)ei;
    const int4* dst4 = (const int4*)(ei + Ee);
    int i = blockIdx.x * 256 + threadIdx.x;          // i < Ee/4 = 800000 exactly
    int4 s = __ldg(&src4[i]);
    int4 d = __ldg(&dst4[i]);
    int sg0 = __ldg(&batch[s.x]), sg1 = __ldg(&batch[s.y]);
    int sg2 = __ldg(&batch[s.z]), sg3 = __ldg(&batch[s.w]);
    int dg0 = __ldg(&batch[d.x]), dg1 = __ldg(&batch[d.y]);
    int dg2 = __ldg(&batch[d.z]), dg3 = __ldg(&batch[d.w]);
    if (sg0 == dg0) atomicAdd(&hist[sg0], 1);
    if (sg1 == dg1) atomicAdd(&hist[sg1], 1);
    if (sg2 == dg2) atomicAdd(&hist[sg2], 1);
    if (sg3 == dg3) atomicAdd(&hist[sg3], 1);
    __syncthreads();
    for (int b = threadIdx.x; b < Bb; b += 256) {
        int v = hist[b];
        if (v) atomicAdd(&g_nedges[b], v);
    }
}

// ---------------- 3) segment-mean pooling: 1 block per (graph, array) ----------
__device__ __forceinline__ int lbound(const int* __restrict__ batch, int key) {
    int lo = 0, hi = Nn;
    while (lo < hi) {
        int mid = (lo + hi) >> 1;
        if (batch[mid] < key) lo = mid + 1; else hi = mid;
    }
    return lo;
}

__global__ void __launch_bounds__(256) k_pool(const float* __restrict__ xg,
                                              const float* __restrict__ xa,
                                              const int* __restrict__ batch) {
    int b = blockIdx.x;
    int half = blockIdx.y;             // 0 -> xg, 1 -> xa
    int t = threadIdx.x;               // 256 threads
    int pr = t >> 7;                   // row parity group
    int c = t & 127;                   // float4 column within H

    __shared__ int bounds[2];
    if (t == 0) bounds[0] = lbound(batch, b);
    if (t == 128) bounds[1] = lbound(batch, b + 1);
    __syncthreads();
    int s0 = bounds[0], e0 = bounds[1];

    const float4* p = ((const float4*)(half ? xa : xg)) + c;
    float4 acc = make_float4(0.f, 0.f, 0.f, 0.f);
    int r = s0 + pr;
    // 4-deep unroll over stride-2 rows: 4 independent loads in flight
    for (; r + 6 < e0; r += 8) {
        float4 v0 = __ldcs(&p[(size_t)(r + 0) * 128]);
        float4 v1 = __ldcs(&p[(size_t)(r + 2) * 128]);
        float4 v2 = __ldcs(&p[(size_t)(r + 4) * 128]);
        float4 v3 = __ldcs(&p[(size_t)(r + 6) * 128]);
        acc.x += v0.x + v1.x + v2.x + v3.x;
        acc.y += v0.y + v1.y + v2.y + v3.y;
        acc.z += v0.z + v1.z + v2.z + v3.z;
        acc.w += v0.w + v1.w + v2.w + v3.w;
    }
    for (; r < e0; r += 2) {
        float4 v = __ldcs(&p[(size_t)r * 128]);
        acc.x += v.x; acc.y += v.y; acc.z += v.z; acc.w += v.w;
    }

    // combine the two parity groups
    __shared__ float4 sacc[128];
    if (pr == 1) sacc[c] = acc;
    __syncthreads();
    if (pr == 0) {
        float4 o = sacc[c];
        float inv = 1.f / fmaxf((float)(e0 - s0), 1.f);
        float4 m = make_float4((acc.x + o.x) * inv, (acc.y + o.y) * inv,
                               (acc.z + o.z) * inv, (acc.w + o.w) * inv);
        int kb = half * Hh + 4 * c;
        g_poolT[kb + 0][b] = m.x;
        g_poolT[kb + 1][b] = m.y;
        g_poolT[kb + 2][b] = m.z;
        g_poolT[kb + 3][b] = m.w;
        *(float4*)&g_pool[b][kb] = m;
    }
}

// ---------------- 4) GEMM1 split-K=2: g_hp[z] = poolT[zK:]^T @ W1[zK:] ---------
__global__ void __launch_bounds__(256) k_gemm1(const float* __restrict__ W1) {
    __shared__ float As[2][BK][BM];   // 16KB
    __shared__ float Ws[2][BK][BN];   // 8KB

    int t = threadIdx.x;
    int n0 = blockIdx.x * BN;
    int m0 = blockIdx.y * BM;
    int z  = blockIdx.z;
    int tn = t & 15;        // owns cols n0 + 2tn, 2tn+1
    int tm = t >> 4;        // owns rows m0 + 4tm .. 4tm+3

    // staging indices
    int ak = t >> 4;             // 0..15   (and ak+16)
    int af = t & 15;             // float4 slot along m
    int wk = t >> 3;             // 0..31
    int wq = t & 7;              // float4 slot along n

    const float* Abase = &g_poolT[z * KHALF][0];
    const float* Wbase = W1 + (size_t)z * KHALF * Hh;
    size_t aIdx0 = (size_t)ak * Bb + m0 + 4 * af;
    size_t aIdx1 = (size_t)(ak + 16) * Bb + m0 + 4 * af;
    size_t wIdx  = (size_t)wk * Hh + n0 + 4 * wq;

    // load chunk 0
    *(float4*)&As[0][ak][4 * af]        = *(const float4*)&Abase[aIdx0];
    *(float4*)&As[0][ak + 16][4 * af]   = *(const float4*)&Abase[aIdx1];
    *(float4*)&Ws[0][wk][4 * wq]        = *(const float4*)&Wbase[wIdx];
    __syncthreads();

    float acc[4][2];
    #pragma unroll
    for (int j = 0; j < 4; j++) { acc[j][0] = 0.f; acc[j][1] = 0.f; }

    for (int c = 0; c < NCH; c++) {
        int nb = c & 1;
        float4 ra0, ra1, rw;
        if (c + 1 < NCH) {
            size_t koff  = (size_t)(c + 1) * BK * Bb;
            size_t kwoff = (size_t)(c + 1) * BK * Hh;
            ra0 = *(const float4*)&Abase[koff + aIdx0];
            ra1 = *(const float4*)&Abase[koff + aIdx1];
            rw  = *(const float4*)&Wbase[kwoff + wIdx];
        }
        #pragma unroll
        for (int k = 0; k < BK; k++) {
            float4 a = *(float4*)&As[nb][k][4 * tm];
            float2 w = *(float2*)&Ws[nb][k][2 * tn];
            acc[0][0] += a.x * w.x; acc[0][1] += a.x * w.y;
            acc[1][0] += a.y * w.x; acc[1][1] += a.y * w.y;
            acc[2][0] += a.z * w.x; acc[2][1] += a.z * w.y;
            acc[3][0] += a.w * w.x; acc[3][1] += a.w * w.y;
        }
        if (c + 1 < NCH) {
            __syncthreads();
            *(float4*)&As[1 - nb][ak][4 * af]      = ra0;
            *(float4*)&As[1 - nb][ak + 16][4 * af] = ra1;
            *(float4*)&Ws[1 - nb][wk][4 * wq]      = rw;
            __syncthreads();
        }
    }

    #pragma unroll
    for (int j = 0; j < 4; j++) {
        *(float2*)&g_hp[z][m0 + 4 * tm + j][n0 + 2 * tn] = make_float2(acc[j][0], acc[j][1]);
    }
}

// ---------------- 5) MLP tail: stats + rank-4 + b1 + LN + relu + MLP + softmax --
__global__ void __launch_bounds__(256) k_mlp2(
    const float* __restrict__ W1, const float* __restrict__ b1,
    const float* __restrict__ lng, const float* __restrict__ lnb,
    const float* __restrict__ W2, const float* __restrict__ b2,
    const float* __restrict__ W3, const float* __restrict__ b3)
{
    __shared__ float comp[RWS][4];
    __shared__ float ts[RWS][Hh];       // post-LN+relu
    __shared__ float red[RWS][8];
    __shared__ float red2[8][3];
    __shared__ float sstat[RWS][3];
    __shared__ float mu_s[RWS], rs_s[RWS];
    __shared__ float red3[8][RWS][2];
    __shared__ float raw_s[RWS][2];

    int t = threadIdx.x;                // 256 threads
    int row0 = blockIdx.x * RWS;
    int lane = t & 31, wid = t >> 5;

    // ---- stats: dot, |g|^2, |a|^2 from row-major pooled means (coalesced)
    #pragma unroll
    for (int r = 0; r < RWS; r++) {
        int b = row0 + r;
        float2 gg = *(const float2*)&g_pool[b][2 * t];
        float2 aa = *(const float2*)&g_pool[b][Hh + 2 * t];
        float dot = gg.x * aa.x + gg.y * aa.y;
        float n2g = gg.x * gg.x + gg.y * gg.y;
        float n2a = aa.x * aa.x + aa.y * aa.y;
        #pragma unroll
        for (int o = 16; o > 0; o >>= 1) {
            dot += __shfl_down_sync(0xFFFFFFFFu, dot, o);
            n2g += __shfl_down_sync(0xFFFFFFFFu, n2g, o);
            n2a += __shfl_down_sync(0xFFFFFFFFu, n2a, o);
        }
        if (lane == 0) { red2[wid][0] = dot; red2[wid][1] = n2g; red2[wid][2] = n2a; }
        __syncthreads();
        if (t < 3) {
            float s = 0.f;
            #pragma unroll
            for (int w = 0; w < 8; w++) s += red2[w][t];
            sstat[r][t] = s;
        }
        __syncthreads();
    }

    // ---- complexity features
    if (t < RWS) {
        int b = row0 + t;
        float cnt = (float)(g_off[b + 1] - g_off[b]);
        float ne  = (float)g_nedges[b];
        float scale   = logf(cnt + 1.f) * (1.f / logf(501.0f));
        float density = ne / (cnt * (cnt - 1.f) + 1e-8f);
        float avgdeg  = ne / (cnt + 1e-8f);
        float avn     = fminf(avgdeg * 0.1f, 1.f);
        float dot = sstat[t][0], n2g = sstat[t][1], n2a = sstat[t][2];
        float na = fmaxf(sqrtf(n2g), 1e-8f);
        float nb = fmaxf(sqrtf(n2a), 1e-8f);
        float cosv = dot / (na * nb);
        comp[t][0] = scale;
        comp[t][1] = density;
        comp[t][2] = avn;
        comp[t][3] = (1.f - cosv) * 0.5f;
    }
    __syncthreads();

    // h = g_hp[0] + g_hp[1] + comp @ W1[1024:1028] + b1 ; thread owns cols 2t,2t+1
    float2 w1t[4];
    #pragma unroll
    for (int j = 0; j < 4; j++)
        w1t[j] = *(const float2*)&W1[(size_t)(KK + j) * Hh + 2 * t];
    float2 bb = ((const float2*)b1)[t];
    float2 h[RWS];
    #pragma unroll
    for (int r = 0; r < RWS; r++) {
        float2 hg0 = *(const float2*)&g_hp[0][row0 + r][2 * t];
        float2 hg1 = *(const float2*)&g_hp[1][row0 + r][2 * t];
        float hx = hg0.x + hg1.x + bb.x, hy = hg0.y + hg1.y + bb.y;
        #pragma unroll
        for (int j = 0; j < 4; j++) {
            hx += comp[r][j] * w1t[j].x;
            hy += comp[r][j] * w1t[j].y;
        }
        h[r] = make_float2(hx, hy);
    }

    // layernorm mean
    #pragma unroll
    for (int r = 0; r < RWS; r++) {
        float p = h[r].x + h[r].y;
        #pragma unroll
        for (int o = 16; o > 0; o >>= 1) p += __shfl_down_sync(0xFFFFFFFFu, p, o);
        if (lane == 0) red[r][wid] = p;
    }
    __syncthreads();
    if (t < RWS) {
        float s = 0.f;
        #pragma unroll
        for (int w = 0; w < 8; w++) s += red[t][w];
        mu_s[t] = s * (1.f / (float)Hh);
    }
    __syncthreads();
    // layernorm var
    #pragma unroll
    for (int r = 0; r < RWS; r++) {
        float dx = h[r].x - mu_s[r], dy = h[r].y - mu_s[r];
        float p = dx * dx + dy * dy;
        #pragma unroll
        for (int o = 16; o > 0; o >>= 1) p += __shfl_down_sync(0xFFFFFFFFu, p, o);
        if (lane == 0) red[r][wid] = p;
    }
    __syncthreads();
    if (t < RWS) {
        float s = 0.f;
        #pragma unroll
        for (int w = 0; w < 8; w++) s += red[t][w];
        rs_s[t] = rsqrtf(s * (1.f / (float)Hh) + 1e-5f);
    }
    __syncthreads();
    {
        float2 gv = ((const float2*)lng)[t];
        float2 bv = ((const float2*)lnb)[t];
        #pragma unroll
        for (int r = 0; r < RWS; r++) {
            float vx = (h[r].x - mu_s[r]) * rs_s[r] * gv.x + bv.x;
            float vy = (h[r].y - mu_s[r]) * rs_s[r] * gv.y + bv.y;
            ts[r][2 * t]     = fmaxf(vx, 0.f);
            ts[r][2 * t + 1] = fmaxf(vy, 0.f);
        }
    }
    __syncthreads();

    // GEMM2: u = relu(ts @ W2 + b2); thread owns col t; prefetched weights
    float u[RWS];
    #pragma unroll
    for (int r = 0; r < RWS; r++) u[r] = 0.f;
    float wr[4];
    #pragma unroll
    for (int j = 0; j < 4; j++) wr[j] = W2[(size_t)j * 256 + t];
    for (int k = 0; k < Hh; k += 4) {
        float wn[4];
        if (k + 4 < Hh) {
            #pragma unroll
            for (int j = 0; j < 4; j++) wn[j] = W2[(size_t)(k + 4 + j) * 256 + t];
        }
        float ta[RWS][4];
        #pragma unroll
        for (int r = 0; r < RWS; r++) {
            float4 q = *(const float4*)&ts[r][k];
            ta[r][0] = q.x; ta[r][1] = q.y; ta[r][2] = q.z; ta[r][3] = q.w;
        }
        #pragma unroll
        for (int kk = 0; kk < 4; kk++) {
            #pragma unroll
            for (int r = 0; r < RWS; r++) u[r] += ta[r][kk] * wr[kk];
        }
        #pragma unroll
        for (int j = 0; j < 4; j++) wr[j] = wn[j];
    }
    float bt = b2[t];
    #pragma unroll
    for (int r = 0; r < RWS; r++) u[r] = fmaxf(u[r] + bt, 0.f);

    // GEMM3: raw[r][c] = sum_j u[r][j]*W3[j][c] + b3[c]
    float w30 = W3[2 * t], w31 = W3[2 * t + 1];
    float p0[RWS], p1[RWS];
    #pragma unroll
    for (int r = 0; r < RWS; r++) { p0[r] = u[r] * w30; p1[r] = u[r] * w31; }
    #pragma unroll
    for (int o = 16; o > 0; o >>= 1) {
        #pragma unroll
        for (int r = 0; r < RWS; r++) {
            p0[r] += __shfl_down_sync(0xFFFFFFFFu, p0[r], o);
            p1[r] += __shfl_down_sync(0xFFFFFFFFu, p1[r], o);
        }
    }
    if (lane == 0) {
        #pragma unroll
        for (int r = 0; r < RWS; r++) { red3[wid][r][0] = p0[r]; red3[wid][r][1] = p1[r]; }
    }
    __syncthreads();
    if (t < RWS * 2) {
        int r = t >> 1, c = t & 1;
        float s = 0.f;
        #pragma unroll
        for (int w = 0; w < 8; w++) s += red3[w][r][c];
        raw_s[r][c] = s + b3[c];
    }
    __syncthreads();
    if (t < RWS) {
        float r0 = raw_s[t][0], r1 = raw_s[t][1];
        float m = fmaxf(r0, r1);
        float e0 = expf(r0 - m), e1 = expf(r1 - m);
        float inv = 1.f / (e0 + e1);
        g_w[row0 + t][0] = e0 * inv;
        g_w[row0 + t][1] = e1 * inv;
    }
}

// ---------------- 6) gated fusion (streaming) -----------------------------------
__global__ void __launch_bounds__(256) k_fuse(const float* __restrict__ xg,
                                              const float* __restrict__ xa,
                                              const int* __restrict__ batch,
                                              float* __restrict__ out) {
    size_t i = (size_t)blockIdx.x * blockDim.x + threadIdx.x;   // float4 index
    if (i >= (size_t)Nn * 128) return;
    int n = (int)(i >> 7);
    int b = __ldg(&batch[n]);
    float w0 = g_w[b][0], w1 = g_w[b][1];
    float4 g = __ldcs(((const float4*)xg) + i);
    float4 a = __ldcs(((const float4*)xa) + i);
    float4 o;
    o.x = w0 * g.x + w1 * a.x;
    o.y = w0 * g.y + w1 * a.y;
    o.z = w0 * g.z + w1 * a.z;
    o.w = w0 * g.w + w1 * a.w;
    __stcs(((float4*)out) + i, o);
}

// ---------------- launch --------------------------------------------------------
extern "C" void kernel_launch(void* const* d_in, const int* in_sizes, int n_in,
                              void* d_out, int out_size) {
    const float* x_ggnn  = (const float*)d_in[0];
    const float* x_appnp = (const float*)d_in[1];
    const int*   edge    = (const int*)d_in[2];
    const int*   batch   = (const int*)d_in[3];
    const float* W1 = (const float*)d_in[4];
    const float* b1 = (const float*)d_in[5];
    const float* lng = (const float*)d_in[6];
    const float* lnb = (const float*)d_in[7];
    const float* W2 = (const float*)d_in[8];
    const float* b2 = (const float*)d_in[9];
    const float* W3 = (const float*)d_in[10];
    const float* b3 = (const float*)d_in[11];
    float* out = (float*)d_out;

    if (s_ok) {
        // fork: side work that only feeds k_mlp2
        cudaEventRecord(evRoot, 0);
        cudaStreamWaitEvent(sA, evRoot, 0);
        k_zero<<<1, Bb, 0, sA>>>();
        k_edges<<<Ee / 4 / 256, 256, 0, sA>>>(edge, batch);
        cudaEventRecord(evA, sA);
        cudaStreamWaitEvent(sB, evRoot, 0);
        k_offsets<<<(Nn + 255) / 256, 256, 0, sB>>>(batch);
        cudaEventRecord(evB, sB);

        // main critical path
        k_pool<<<dim3(Bb, 2), 256>>>(x_ggnn, x_appnp, batch);
        k_gemm1<<<dim3(Hh / BN, Bb / BM, 2), 256>>>(W1);
        cudaStreamWaitEvent(0, evA, 0);
        cudaStreamWaitEvent(0, evB, 0);
        k_mlp2<<<Bb / RWS, 256>>>(W1, b1, lng, lnb, W2, b2, W3, b3);
        k_fuse<<<(Nn * 128 + 255) / 256, 256>>>(x_ggnn, x_appnp, batch, out);
    } else {
        // serial fallback
        k_zero<<<1, Bb>>>();
        k_edges<<<Ee / 4 / 256, 256>>>(edge, batch);
        k_offsets<<<(Nn + 255) / 256, 256>>>(batch);
        k_pool<<<dim3(Bb, 2), 256>>>(x_ggnn, x_appnp, batch);
        k_gemm1<<<dim3(Hh / BN, Bb / BM, 2), 256>>>(W1);
        k_mlp2<<<Bb / RWS, 256>>>(W1, b1, lng, lnb, W2, b2, W3, b3);
        k_fuse<<<(Nn * 128 + 255) / 256, 256>>>(x_ggnn, x_appnp, batch, out);
    }
}

// round 6
// speedup vs baseline: 1.8331x; 1.0478x over previous
#include <cuda_runtime.h>
#include <math.h>

#define Nn 100000
#define Ee 3200000
#define Hh 512
#define Bb 512
#define RWS 4      // rows per MLP block
#define BM 64
#define BN 32
#define BK 32
#define KK 1024    // GEMM1 K (pooled part only)
#define KHALF 512
#define NCH (KHALF / BK)   // 16 chunks per K-half

// ---------------- scratch (static device memory, no allocation) ----------------
__device__ int   g_off[Bb + 1];
__device__ int   g_nedges[Bb];
__device__ float g_poolT[KK][Bb];     // transposed pooled means: [feature][graph]
__device__ float g_pool[Bb][KK];      // row-major pooled means (for stats)
__device__ float g_hp[2][Bb][Hh];     // split-K GEMM1 partial outputs
__device__ float g_w[Bb][2];          // softmax gate weights

// ---------------- streams/events for fork-join (host-side, static init) --------
static cudaStream_t sA = 0, sB = 0;
static cudaEvent_t evRoot = 0, evA = 0, evB = 0;
static bool s_ok = false;
struct StreamInit {
    StreamInit() {
        bool ok = true;
        ok &= cudaStreamCreateWithFlags(&sA, cudaStreamNonBlocking) == cudaSuccess;
        ok &= cudaStreamCreateWithFlags(&sB, cudaStreamNonBlocking) == cudaSuccess;
        ok &= cudaEventCreateWithFlags(&evRoot, cudaEventDisableTiming) == cudaSuccess;
        ok &= cudaEventCreateWithFlags(&evA, cudaEventDisableTiming) == cudaSuccess;
        ok &= cudaEventCreateWithFlags(&evB, cudaEventDisableTiming) == cudaSuccess;
        s_ok = ok;
    }
};
static StreamInit s_init;

// ---------------- 0) zero nedges ------------------------------------------------
__global__ void k_zero() { g_nedges[threadIdx.x] = 0; }

// ---------------- 1) graph boundaries from sorted batch -------------------------
__global__ void k_offsets(const int* __restrict__ batch) {
    int i = blockIdx.x * blockDim.x + threadIdx.x;
    if (i >= Nn) return;
    int c = batch[i];
    int p = (i == 0) ? -1 : batch[i - 1];
    for (int b = p + 1; b <= c; b++) g_off[b] = i;
    if (i == Nn - 1) {
        for (int b = c + 1; b <= Bb; b++) g_off[b] = Nn;
    }
}

// ---------------- 2) same-graph edge histogram (int4-vectorized, one pass) -----
__global__ void __launch_bounds__(256) k_edges(const int* __restrict__ ei,
                                               const int* __restrict__ batch) {
    __shared__ int hist[Bb];
    for (int i = threadIdx.x; i < Bb; i += 256) hist[i] = 0;
    __syncthreads();
    const int4* src4 = (const int4*)ei;
    const int4* dst4 = (const int4*)(ei + Ee);
    int i = blockIdx.x * 256 + threadIdx.x;          // i < Ee/4 = 800000 exactly
    int4 s = __ldg(&src4[i]);
    int4 d = __ldg(&dst4[i]);
    int sg0 = __ldg(&batch[s.x]), sg1 = __ldg(&batch[s.y]);
    int sg2 = __ldg(&batch[s.z]), sg3 = __ldg(&batch[s.w]);
    int dg0 = __ldg(&batch[d.x]), dg1 = __ldg(&batch[d.y]);
    int dg2 = __ldg(&batch[d.z]), dg3 = __ldg(&batch[d.w]);
    if (sg0 == dg0) atomicAdd(&hist[sg0], 1);
    if (sg1 == dg1) atomicAdd(&hist[sg1], 1);
    if (sg2 == dg2) atomicAdd(&hist[sg2], 1);
    if (sg3 == dg3) atomicAdd(&hist[sg3], 1);
    __syncthreads();
    for (int b = threadIdx.x; b < Bb; b += 256) {
        int v = hist[b];
        if (v) atomicAdd(&g_nedges[b], v);
    }
}

// ---------------- 3) segment-mean pooling: 1 block per (graph, array) ----------
__device__ __forceinline__ int lbound(const int* __restrict__ batch, int key) {
    int lo = 0, hi = Nn;
    while (lo < hi) {
        int mid = (lo + hi) >> 1;
        if (batch[mid] < key) lo = mid + 1; else hi = mid;
    }
    return lo;
}

__global__ void __launch_bounds__(256) k_pool(const float* __restrict__ xg,
                                              const float* __restrict__ xa,
                                              const int* __restrict__ batch) {
    int b = blockIdx.x;
    int half = blockIdx.y;             // 0 -> xg, 1 -> xa
    int t = threadIdx.x;               // 256 threads
    int pr = t >> 7;                   // row parity group
    int c = t & 127;                   // float4 column within H

    __shared__ int bounds[2];
    if (t == 0) bounds[0] = lbound(batch, b);
    if (t == 128) bounds[1] = lbound(batch, b + 1);
    __syncthreads();
    int s0 = bounds[0], e0 = bounds[1];

    const float4* p = ((const float4*)(half ? xa : xg)) + c;
    float4 acc = make_float4(0.f, 0.f, 0.f, 0.f);
    int r = s0 + pr;
    // 8 independent loads in flight per iteration (stride-2 rows, step 16)
    for (; r + 14 < e0; r += 16) {
        float4 v0 = __ldcs(&p[(size_t)(r +  0) * 128]);
        float4 v1 = __ldcs(&p[(size_t)(r +  2) * 128]);
        float4 v2 = __ldcs(&p[(size_t)(r +  4) * 128]);
        float4 v3 = __ldcs(&p[(size_t)(r +  6) * 128]);
        float4 v4 = __ldcs(&p[(size_t)(r +  8) * 128]);
        float4 v5 = __ldcs(&p[(size_t)(r + 10) * 128]);
        float4 v6 = __ldcs(&p[(size_t)(r + 12) * 128]);
        float4 v7 = __ldcs(&p[(size_t)(r + 14) * 128]);
        acc.x += (v0.x + v1.x) + (v2.x + v3.x) + ((v4.x + v5.x) + (v6.x + v7.x));
        acc.y += (v0.y + v1.y) + (v2.y + v3.y) + ((v4.y + v5.y) + (v6.y + v7.y));
        acc.z += (v0.z + v1.z) + (v2.z + v3.z) + ((v4.z + v5.z) + (v6.z + v7.z));
        acc.w += (v0.w + v1.w) + (v2.w + v3.w) + ((v4.w + v5.w) + (v6.w + v7.w));
    }
    for (; r < e0; r += 2) {
        float4 v = __ldcs(&p[(size_t)r * 128]);
        acc.x += v.x; acc.y += v.y; acc.z += v.z; acc.w += v.w;
    }

    // combine the two parity groups
    __shared__ float4 sacc[128];
    if (pr == 1) sacc[c] = acc;
    __syncthreads();
    if (pr == 0) {
        float4 o = sacc[c];
        float inv = 1.f / fmaxf((float)(e0 - s0), 1.f);
        float4 m = make_float4((acc.x + o.x) * inv, (acc.y + o.y) * inv,
                               (acc.z + o.z) * inv, (acc.w + o.w) * inv);
        int kb = half * Hh + 4 * c;
        g_poolT[kb + 0][b] = m.x;
        g_poolT[kb + 1][b] = m.y;
        g_poolT[kb + 2][b] = m.z;
        g_poolT[kb + 3][b] = m.w;
        *(float4*)&g_pool[b][kb] = m;
    }
}

// ---------------- 4) GEMM1 split-K=2: g_hp[z] = poolT[zK:]^T @ W1[zK:] ---------
__global__ void __launch_bounds__(256) k_gemm1(const float* __restrict__ W1) {
    __shared__ float As[2][BK][BM];   // 16KB
    __shared__ float Ws[2][BK][BN];   // 8KB

    int t = threadIdx.x;
    int n0 = blockIdx.x * BN;
    int m0 = blockIdx.y * BM;
    int z  = blockIdx.z;
    int tn = t & 15;        // owns cols n0 + 2tn, 2tn+1
    int tm = t >> 4;        // owns rows m0 + 4tm .. 4tm+3

    // staging indices
    int ak = t >> 4;             // 0..15   (and ak+16)
    int af = t & 15;             // float4 slot along m
    int wk = t >> 3;             // 0..31
    int wq = t & 7;              // float4 slot along n

    const float* Abase = &g_poolT[z * KHALF][0];
    const float* Wbase = W1 + (size_t)z * KHALF * Hh;
    size_t aIdx0 = (size_t)ak * Bb + m0 + 4 * af;
    size_t aIdx1 = (size_t)(ak + 16) * Bb + m0 + 4 * af;
    size_t wIdx  = (size_t)wk * Hh + n0 + 4 * wq;

    // load chunk 0
    *(float4*)&As[0][ak][4 * af]        = *(const float4*)&Abase[aIdx0];
    *(float4*)&As[0][ak + 16][4 * af]   = *(const float4*)&Abase[aIdx1];
    *(float4*)&Ws[0][wk][4 * wq]        = *(const float4*)&Wbase[wIdx];
    __syncthreads();

    float acc[4][2];
    #pragma unroll
    for (int j = 0; j < 4; j++) { acc[j][0] = 0.f; acc[j][1] = 0.f; }

    for (int c = 0; c < NCH; c++) {
        int nb = c & 1;
        float4 ra0, ra1, rw;
        if (c + 1 < NCH) {
            size_t koff  = (size_t)(c + 1) * BK * Bb;
            size_t kwoff = (size_t)(c + 1) * BK * Hh;
            ra0 = *(const float4*)&Abase[koff + aIdx0];
            ra1 = *(const float4*)&Abase[koff + aIdx1];
            rw  = *(const float4*)&Wbase[kwoff + wIdx];
        }
        #pragma unroll
        for (int k = 0; k < BK; k++) {
            float4 a = *(float4*)&As[nb][k][4 * tm];
            float2 w = *(float2*)&Ws[nb][k][2 * tn];
            acc[0][0] += a.x * w.x; acc[0][1] += a.x * w.y;
            acc[1][0] += a.y * w.x; acc[1][1] += a.y * w.y;
            acc[2][0] += a.z * w.x; acc[2][1] += a.z * w.y;
            acc[3][0] += a.w * w.x; acc[3][1] += a.w * w.y;
        }
        if (c + 1 < NCH) {
            __syncthreads();
            *(float4*)&As[1 - nb][ak][4 * af]      = ra0;
            *(float4*)&As[1 - nb][ak + 16][4 * af] = ra1;
            *(float4*)&Ws[1 - nb][wk][4 * wq]      = rw;
            __syncthreads();
        }
    }

    #pragma unroll
    for (int j = 0; j < 4; j++) {
        *(float2*)&g_hp[z][m0 + 4 * tm + j][n0 + 2 * tn] = make_float2(acc[j][0], acc[j][1]);
    }
}

// ---------------- 5) MLP tail: stats + rank-4 + b1 + LN + relu + MLP + softmax --
__global__ void __launch_bounds__(256) k_mlp2(
    const float* __restrict__ W1, const float* __restrict__ b1,
    const float* __restrict__ lng, const float* __restrict__ lnb,
    const float* __restrict__ W2, const float* __restrict__ b2,
    const float* __restrict__ W3, const float* __restrict__ b3)
{
    __shared__ float comp[RWS][4];
    __shared__ float ts[RWS][Hh];       // post-LN+relu
    __shared__ float red[RWS][8];
    __shared__ float red2[8][3];
    __shared__ float sstat[RWS][3];
    __shared__ float mu_s[RWS], rs_s[RWS];
    __shared__ float red3[8][RWS][2];
    __shared__ float raw_s[RWS][2];

    int t = threadIdx.x;                // 256 threads
    int row0 = blockIdx.x * RWS;
    int lane = t & 31, wid = t >> 5;

    // ---- stats: dot, |g|^2, |a|^2 from row-major pooled means (coalesced)
    #pragma unroll
    for (int r = 0; r < RWS; r++) {
        int b = row0 + r;
        float2 gg = *(const float2*)&g_pool[b][2 * t];
        float2 aa = *(const float2*)&g_pool[b][Hh + 2 * t];
        float dot = gg.x * aa.x + gg.y * aa.y;
        float n2g = gg.x * gg.x + gg.y * gg.y;
        float n2a = aa.x * aa.x + aa.y * aa.y;
        #pragma unroll
        for (int o = 16; o > 0; o >>= 1) {
            dot += __shfl_down_sync(0xFFFFFFFFu, dot, o);
            n2g += __shfl_down_sync(0xFFFFFFFFu, n2g, o);
            n2a += __shfl_down_sync(0xFFFFFFFFu, n2a, o);
        }
        if (lane == 0) { red2[wid][0] = dot; red2[wid][1] = n2g; red2[wid][2] = n2a; }
        __syncthreads();
        if (t < 3) {
            float s = 0.f;
            #pragma unroll
            for (int w = 0; w < 8; w++) s += red2[w][t];
            sstat[r][t] = s;
        }
        __syncthreads();
    }

    // ---- complexity features
    if (t < RWS) {
        int b = row0 + t;
        float cnt = (float)(g_off[b + 1] - g_off[b]);
        float ne  = (float)g_nedges[b];
        float scale   = logf(cnt + 1.f) * (1.f / logf(501.0f));
        float density = ne / (cnt * (cnt - 1.f) + 1e-8f);
        float avgdeg  = ne / (cnt + 1e-8f);
        float avn     = fminf(avgdeg * 0.1f, 1.f);
        float dot = sstat[t][0], n2g = sstat[t][1], n2a = sstat[t][2];
        float na = fmaxf(sqrtf(n2g), 1e-8f);
        float nb = fmaxf(sqrtf(n2a), 1e-8f);
        float cosv = dot / (na * nb);
        comp[t][0] = scale;
        comp[t][1] = density;
        comp[t][2] = avn;
        comp[t][3] = (1.f - cosv) * 0.5f;
    }
    __syncthreads();

    // h = g_hp[0] + g_hp[1] + comp @ W1[1024:1028] + b1 ; thread owns cols 2t,2t+1
    float2 w1t[4];
    #pragma unroll
    for (int j = 0; j < 4; j++)
        w1t[j] = *(const float2*)&W1[(size_t)(KK + j) * Hh + 2 * t];
    float2 bb = ((const float2*)b1)[t];
    float2 h[RWS];
    #pragma unroll
    for (int r = 0; r < RWS; r++) {
        float2 hg0 = *(const float2*)&g_hp[0][row0 + r][2 * t];
        float2 hg1 = *(const float2*)&g_hp[1][row0 + r][2 * t];
        float hx = hg0.x + hg1.x + bb.x, hy = hg0.y + hg1.y + bb.y;
        #pragma unroll
        for (int j = 0; j < 4; j++) {
            hx += comp[r][j] * w1t[j].x;
            hy += comp[r][j] * w1t[j].y;
        }
        h[r] = make_float2(hx, hy);
    }

    // layernorm mean
    #pragma unroll
    for (int r = 0; r < RWS; r++) {
        float p = h[r].x + h[r].y;
        #pragma unroll
        for (int o = 16; o > 0; o >>= 1) p += __shfl_down_sync(0xFFFFFFFFu, p, o);
        if (lane == 0) red[r][wid] = p;
    }
    __syncthreads();
    if (t < RWS) {
        float s = 0.f;
        #pragma unroll
        for (int w = 0; w < 8; w++) s += red[t][w];
        mu_s[t] = s * (1.f / (float)Hh);
    }
    __syncthreads();
    // layernorm var
    #pragma unroll
    for (int r = 0; r < RWS; r++) {
        float dx = h[r].x - mu_s[r], dy = h[r].y - mu_s[r];
        float p = dx * dx + dy * dy;
        #pragma unroll
        for (int o = 16; o > 0; o >>= 1) p += __shfl_down_sync(0xFFFFFFFFu, p, o);
        if (lane == 0) red[r][wid] = p;
    }
    __syncthreads();
    if (t < RWS) {
        float s = 0.f;
        #pragma unroll
        for (int w = 0; w < 8; w++) s += red[t][w];
        rs_s[t] = rsqrtf(s * (1.f / (float)Hh) + 1e-5f);
    }
    __syncthreads();
    {
        float2 gv = ((const float2*)lng)[t];
        float2 bv = ((const float2*)lnb)[t];
        #pragma unroll
        for (int r = 0; r < RWS; r++) {
            float vx = (h[r].x - mu_s[r]) * rs_s[r] * gv.x + bv.x;
            float vy = (h[r].y - mu_s[r]) * rs_s[r] * gv.y + bv.y;
            ts[r][2 * t]     = fmaxf(vx, 0.f);
            ts[r][2 * t + 1] = fmaxf(vy, 0.f);
        }
    }
    __syncthreads();

    // GEMM2: u = relu(ts @ W2 + b2); thread owns col t; prefetched weights
    float u[RWS];
    #pragma unroll
    for (int r = 0; r < RWS; r++) u[r] = 0.f;
    float wr[4];
    #pragma unroll
    for (int j = 0; j < 4; j++) wr[j] = W2[(size_t)j * 256 + t];
    for (int k = 0; k < Hh; k += 4) {
        float wn[4];
        if (k + 4 < Hh) {
            #pragma unroll
            for (int j = 0; j < 4; j++) wn[j] = W2[(size_t)(k + 4 + j) * 256 + t];
        }
        float ta[RWS][4];
        #pragma unroll
        for (int r = 0; r < RWS; r++) {
            float4 q = *(const float4*)&ts[r][k];
            ta[r][0] = q.x; ta[r][1] = q.y; ta[r][2] = q.z; ta[r][3] = q.w;
        }
        #pragma unroll
        for (int kk = 0; kk < 4; kk++) {
            #pragma unroll
            for (int r = 0; r < RWS; r++) u[r] += ta[r][kk] * wr[kk];
        }
        #pragma unroll
        for (int j = 0; j < 4; j++) wr[j] = wn[j];
    }
    float bt = b2[t];
    #pragma unroll
    for (int r = 0; r < RWS; r++) u[r] = fmaxf(u[r] + bt, 0.f);

    // GEMM3: raw[r][c] = sum_j u[r][j]*W3[j][c] + b3[c]
    float w30 = W3[2 * t], w31 = W3[2 * t + 1];
    float p0[RWS], p1[RWS];
    #pragma unroll
    for (int r = 0; r < RWS; r++) { p0[r] = u[r] * w30; p1[r] = u[r] * w31; }
    #pragma unroll
    for (int o = 16; o > 0; o >>= 1) {
        #pragma unroll
        for (int r = 0; r < RWS; r++) {
            p0[r] += __shfl_down_sync(0xFFFFFFFFu, p0[r], o);
            p1[r] += __shfl_down_sync(0xFFFFFFFFu, p1[r], o);
        }
    }
    if (lane == 0) {
        #pragma unroll
        for (int r = 0; r < RWS; r++) { red3[wid][r][0] = p0[r]; red3[wid][r][1] = p1[r]; }
    }
    __syncthreads();
    if (t < RWS * 2) {
        int r = t >> 1, c = t & 1;
        float s = 0.f;
        #pragma unroll
        for (int w = 0; w < 8; w++) s += red3[w][r][c];
        raw_s[r][c] = s + b3[c];
    }
    __syncthreads();
    if (t < RWS) {
        float r0 = raw_s[t][0], r1 = raw_s[t][1];
        float m = fmaxf(r0, r1);
        float e0 = expf(r0 - m), e1 = expf(r1 - m);
        float inv = 1.f / (e0 + e1);
        g_w[row0 + t][0] = e0 * inv;
        g_w[row0 + t][1] = e1 * inv;
    }
}

// ---------------- 6) gated fusion (streaming, 2 float4 per thread) --------------
__global__ void __launch_bounds__(256) k_fuse(const float* __restrict__ xg,
                                              const float* __restrict__ xa,
                                              const int* __restrict__ batch,
                                              float* __restrict__ out) {
    size_t i0 = (size_t)blockIdx.x * 512 + threadIdx.x;   // float4 index
    size_t i1 = i0 + 256;
    // Nn*128 = 12.8M divisible by 512 -> no bounds check needed
    int n0 = (int)(i0 >> 7);
    int n1 = (int)(i1 >> 7);
    int b0 = __ldg(&batch[n0]);
    int b1 = __ldg(&batch[n1]);
    float4 g0 = __ldcs(((const float4*)xg) + i0);
    float4 a0 = __ldcs(((const float4*)xa) + i0);
    float4 g1 = __ldcs(((const float4*)xg) + i1);
    float4 a1 = __ldcs(((const float4*)xa) + i1);
    float w00 = g_w[b0][0], w01 = g_w[b0][1];
    float w10 = g_w[b1][0], w11 = g_w[b1][1];
    float4 o0, o1;
    o0.x = w00 * g0.x + w01 * a0.x;
    o0.y = w00 * g0.y + w01 * a0.y;
    o0.z = w00 * g0.z + w01 * a0.z;
    o0.w = w00 * g0.w + w01 * a0.w;
    o1.x = w10 * g1.x + w11 * a1.x;
    o1.y = w10 * g1.y + w11 * a1.y;
    o1.z = w10 * g1.z + w11 * a1.z;
    o1.w = w10 * g1.w + w11 * a1.w;
    __stcs(((float4*)out) + i0, o0);
    __stcs(((float4*)out) + i1, o1);
}

// ---------------- launch --------------------------------------------------------
extern "C" void kernel_launch(void* const* d_in, const int* in_sizes, int n_in,
                              void* d_out, int out_size) {
    const float* x_ggnn  = (const float*)d_in[0];
    const float* x_appnp = (const float*)d_in[1];
    const int*   edge    = (const int*)d_in[2];
    const int*   batch   = (const int*)d_in[3];
    const float* W1 = (const float*)d_in[4];
    const float* b1 = (const float*)d_in[5];
    const float* lng = (const float*)d_in[6];
    const float* lnb = (const float*)d_in[7];
    const float* W2 = (const float*)d_in[8];
    const float* b2 = (const float*)d_in[9];
    const float* W3 = (const float*)d_in[10];
    const float* b3 = (const float*)d_in[11];
    float* out = (float*)d_out;

    if (s_ok) {
        // fork: side work that only feeds k_mlp2
        cudaEventRecord(evRoot, 0);
        cudaStreamWaitEvent(sA, evRoot, 0);
        k_zero<<<1, Bb, 0, sA>>>();
        k_edges<<<Ee / 4 / 256, 256, 0, sA>>>(edge, batch);
        cudaEventRecord(evA, sA);
        cudaStreamWaitEvent(sB, evRoot, 0);
        k_offsets<<<(Nn + 255) / 256, 256, 0, sB>>>(batch);
        cudaEventRecord(evB, sB);

        // main critical path
        k_pool<<<dim3(Bb, 2), 256>>>(x_ggnn, x_appnp, batch);
        k_gemm1<<<dim3(Hh / BN, Bb / BM, 2), 256>>>(W1);
        cudaStreamWaitEvent(0, evA, 0);
        cudaStreamWaitEvent(0, evB, 0);
        k_mlp2<<<Bb / RWS, 256>>>(W1, b1, lng, lnb, W2, b2, W3, b3);
        k_fuse<<<(Nn * 128) / 512, 256>>>(x_ggnn, x_appnp, batch, out);
    } else {
        // serial fallback
        k_zero<<<1, Bb>>>();
        k_edges<<<Ee / 4 / 256, 256>>>(edge, batch);
        k_offsets<<<(Nn + 255) / 256, 256>>>(batch);
        k_pool<<<dim3(Bb, 2), 256>>>(x_ggnn, x_appnp, batch);
        k_gemm1<<<dim3(Hh / BN, Bb / BM, 2), 256>>>(W1);
        k_mlp2<<<Bb / RWS, 256>>>(W1, b1, lng, lnb, W2, b2, W3, b3);
        k_fuse<<<(Nn * 128) / 512, 256>>>(x_ggnn, x_appnp, batch, out);
    }
}